// round 14
// baseline (speedup 1.0000x reference)
#include <cuda_runtime.h>
#include <cuda_bf16.h>
#include <math.h>
#include <stdint.h>

#define Bz 20
#define Sz 256
#define Vz 32000
#define Hz 1024
#define G4H 4096

// ---------------- scratch (static device globals — allocation-free) ----------------
__device__ float g_xproj[Sz * Bz * G4H];                 // [S][B][4H]
__device__ __nv_bfloat16 g_A_hi[Sz * Bz * Hz];           // GEMM A operand (hi)
__device__ __nv_bfloat16 g_A_lo[Sz * Bz * Hz];           // GEMM A operand (lo)
__device__ __nv_bfloat16 g_hAh[2][32 * Hz];              // h state hi (ping-pong)
__device__ __nv_bfloat16 g_hAl[2][32 * Hz];              // h state lo
__device__ __nv_bfloat16 g_w1_hi[G4H * Hz];              // x2h splits
__device__ __nv_bfloat16 g_w1_lo[G4H * Hz];
__device__ __nv_bfloat16 g_w2_hi[G4H * Hz];
__device__ __nv_bfloat16 g_w2_lo[G4H * Hz];
__device__ __nv_bfloat16 g_dw_hi[Vz * Hz];
__device__ __nv_bfloat16 g_dw_lo[Vz * Hz];
__device__ __nv_bfloat16 g_wr1_hi[G4H * Hz];             // h2h permuted splits: row n=d*4+g
__device__ __nv_bfloat16 g_wr1_lo[G4H * Hz];
__device__ __nv_bfloat16 g_wr2_hi[G4H * Hz];
__device__ __nv_bfloat16 g_wr2_lo[G4H * Hz];
__device__ int g_flags[512];                             // per-block step flags, 16B stride

// ---------------- PTX helpers (portable) ----------------
__device__ __forceinline__ uint32_t smem_u32(const void* p) {
    uint32_t a;
    asm("{ .reg .u64 t; cvta.to.shared.u64 t, %1; cvt.u32.u64 %0, t; }" : "=r"(a) : "l"(p));
    return a;
}
#define CPASYNC16(dst, src) \
    asm volatile("cp.async.cg.shared.global [%0], [%1], 16;" :: "r"(dst), "l"(src))
#define CPCOMMIT() asm volatile("cp.async.commit_group;" ::: "memory")
#define CPWAIT(n)  asm volatile("cp.async.wait_group %0;" :: "n"(n) : "memory")
#define LDSM4(R, addr)                                                                  \
    asm volatile("ldmatrix.sync.aligned.m8n8.x4.shared.b16 {%0,%1,%2,%3}, [%4];"        \
        : "=r"((R)[0]), "=r"((R)[1]), "=r"((R)[2]), "=r"((R)[3]) : "r"(addr))
#define MMA16816(D, A, B0, B1)                                                          \
    asm volatile("mma.sync.aligned.m16n8k16.row.col.f32.bf16.bf16.f32 "                 \
        "{%0,%1,%2,%3}, {%4,%5,%6,%7}, {%8,%9}, {%0,%1,%2,%3};"                         \
        : "+f"((D)[0]), "+f"((D)[1]), "+f"((D)[2]), "+f"((D)[3])                        \
        : "r"((A)[0]), "r"((A)[1]), "r"((A)[2]), "r"((A)[3]), "r"(B0), "r"(B1))

// ---------------- fp32 -> bf16 hi/lo split helpers ----------------
__device__ __forceinline__ void split4(float4 v, uint2& hi, uint2& lo) {
    float f[4] = {v.x, v.y, v.z, v.w};
    uint32_t h[4], l[4];
#pragma unroll
    for (int i = 0; i < 4; i++) {
        __nv_bfloat16 bh = __float2bfloat16(f[i]);
        __nv_bfloat16 bl = __float2bfloat16(f[i] - __bfloat162float(bh));
        h[i] = __bfloat16_as_ushort(bh);
        l[i] = __bfloat16_as_ushort(bl);
    }
    hi.x = h[0] | (h[1] << 16); hi.y = h[2] | (h[3] << 16);
    lo.x = l[0] | (l[1] << 16); lo.y = l[2] | (l[3] << 16);
}

__global__ void split_w(const float* __restrict__ w, __nv_bfloat16* __restrict__ hi,
                        __nv_bfloat16* __restrict__ lo, int n4) {
    int i = blockIdx.x * 256 + threadIdx.x;
    if (i >= n4) return;
    uint2 h, l;
    split4(reinterpret_cast<const float4*>(w)[i], h, l);
    reinterpret_cast<uint2*>(hi)[i] = h;
    reinterpret_cast<uint2*>(lo)[i] = l;
}

// permuted h2h split: out row n = d*4+g  <-  in row g*1024+d
__global__ void perm_split_w(const float* __restrict__ w, __nv_bfloat16* __restrict__ hi,
                             __nv_bfloat16* __restrict__ lo) {
    int idx = blockIdx.x * 256 + threadIdx.x;
    int n  = idx >> 8;
    int k4 = idx & 255;
    int d = n >> 2, g = n & 3;
    uint2 h, l;
    split4(reinterpret_cast<const float4*>(w)[(g * Hz + d) * 256 + k4], h, l);
    reinterpret_cast<uint2*>(hi)[n * 256 + k4] = h;
    reinterpret_cast<uint2*>(lo)[n * 256 + k4] = l;
}

// split h0 fp32 [20][1024] into hA buffer rows 0..19
__global__ void split_h0(const float* __restrict__ h0, __nv_bfloat16* __restrict__ hi,
                         __nv_bfloat16* __restrict__ lo) {
    int i = blockIdx.x * 256 + threadIdx.x;
    uint2 h, l;
    split4(reinterpret_cast<const float4*>(h0)[i], h, l);
    reinterpret_cast<uint2*>(hi)[i] = h;
    reinterpret_cast<uint2*>(lo)[i] = l;
}

// ---------------- embedding gather -> A hi/lo directly ----------------
__global__ void embed_split(const int* __restrict__ ids, const float* __restrict__ emb,
                            __nv_bfloat16* __restrict__ Ahi, __nv_bfloat16* __restrict__ Alo) {
    int gid = blockIdx.x * 256 + threadIdx.x;
    int c4  = gid & 255;
    int sb  = gid >> 8;
    int b   = sb % Bz;
    int s   = sb / Bz;
    int tok = ids[b * Sz + s];
    float4 v = reinterpret_cast<const float4*>(emb)[(size_t)tok * 256 + c4];
    uint2 h, l;
    split4(v, h, l);
    reinterpret_cast<uint2*>(Ahi)[gid] = h;
    reinterpret_cast<uint2*>(Alo)[gid] = l;
}

// ---------------- HMMA bf16-split GEMM 128x128 (validated R7) ----------------
#define BK 32
#define SROW 80
#define TILEB (128 * SROW)
#define BUFB  (4 * TILEB)
#define GEMM_SMEM (2 * BUFB)

__global__ __launch_bounds__(256, 1) void gemm_mma(
    const __nv_bfloat16* __restrict__ Ahi, const __nv_bfloat16* __restrict__ Alo,
    const __nv_bfloat16* __restrict__ Whi, const __nv_bfloat16* __restrict__ Wlo,
    const float* __restrict__ bias, float* __restrict__ C, int N) {
    extern __shared__ char smdyn[];
    const uint32_t sb = smem_u32(smdyn);
    const int tid  = threadIdx.x;
    const int wid  = tid >> 5;
    const int lane = tid & 31;
    const int bm   = blockIdx.x * 128;
    const int bn   = blockIdx.y * 128;
    const int wm   = (wid & 3) * 32;
    const int wn   = (wid >> 2) * 64;

    float acc[2][8][4];
#pragma unroll
    for (int mf = 0; mf < 2; mf++)
#pragma unroll
        for (int nf = 0; nf < 8; nf++)
#pragma unroll
            for (int r = 0; r < 4; r++) acc[mf][nf][r] = 0.0f;

    const uint32_t a_off = (uint32_t)((wm + (lane & 15)) * SROW + (lane >> 4) * 16);
    const uint32_t b_off = (uint32_t)((wn + (lane & 7) + ((lane >> 4) << 3)) * SROW +
                                      ((lane >> 3) & 1) * 16);

    auto prefetch = [&](int ch, int buf) {
        const int kt = ch * BK;
        const uint32_t base = sb + buf * BUFB;
#pragma unroll
        for (int i = 0; i < 8; i++) {
            int id  = tid + i * 256;
            int sel = id >> 9;
            int u   = id & 511;
            int r   = u >> 2;
            int c4  = u & 3;
            const __nv_bfloat16* src;
            if (sel == 0)      src = Ahi + (size_t)(bm + r) * Hz + kt + c4 * 8;
            else if (sel == 1) src = Alo + (size_t)(bm + r) * Hz + kt + c4 * 8;
            else if (sel == 2) src = Whi + (size_t)(bn + r) * Hz + kt + c4 * 8;
            else               src = Wlo + (size_t)(bn + r) * Hz + kt + c4 * 8;
            CPASYNC16(base + sel * TILEB + (uint32_t)(r * SROW + c4 * 16), src);
        }
    };

    prefetch(0, 0);
    CPCOMMIT();

    const int NCH = Hz / BK;
    for (int ch = 0; ch < NCH; ch++) {
        const int buf = ch & 1;
        if (ch + 1 < NCH) {
            prefetch(ch + 1, buf ^ 1);
            CPCOMMIT();
            CPWAIT(1);
        } else {
            CPWAIT(0);
        }
        __syncthreads();

        const uint32_t ah_b = sb + buf * BUFB;
        const uint32_t al_b = ah_b + TILEB;
        const uint32_t wh_b = ah_b + 2 * TILEB;
        const uint32_t wl_b = ah_b + 3 * TILEB;

#pragma unroll
        for (int k16 = 0; k16 < 2; k16++) {
            const uint32_t ko = k16 * 32;
            uint32_t ah[2][4], al[2][4], bh[4][4], bl[4][4];
#pragma unroll
            for (int mf = 0; mf < 2; mf++) {
                LDSM4(ah[mf], ah_b + a_off + mf * 16 * SROW + ko);
                LDSM4(al[mf], al_b + a_off + mf * 16 * SROW + ko);
            }
#pragma unroll
            for (int nf2 = 0; nf2 < 4; nf2++) {
                LDSM4(bh[nf2], wh_b + b_off + nf2 * 16 * SROW + ko);
                LDSM4(bl[nf2], wl_b + b_off + nf2 * 16 * SROW + ko);
            }
#pragma unroll
            for (int mf = 0; mf < 2; mf++)
#pragma unroll
                for (int nf = 0; nf < 8; nf++) {
                    uint32_t b0h = bh[nf >> 1][(nf & 1) * 2 + 0];
                    uint32_t b1h = bh[nf >> 1][(nf & 1) * 2 + 1];
                    uint32_t b0l = bl[nf >> 1][(nf & 1) * 2 + 0];
                    uint32_t b1l = bl[nf >> 1][(nf & 1) * 2 + 1];
                    MMA16816(acc[mf][nf], ah[mf], b0h, b1h);
                    MMA16816(acc[mf][nf], ah[mf], b0l, b1l);
                    MMA16816(acc[mf][nf], al[mf], b0h, b1h);
                }
        }
        __syncthreads();
    }

    const int g  = lane >> 2;
    const int tg = lane & 3;
#pragma unroll
    for (int mf = 0; mf < 2; mf++) {
        int m0 = bm + wm + mf * 16 + g;
        int m1 = m0 + 8;
        size_t rb0 = (size_t)m0 * N;
        size_t rb1 = (size_t)m1 * N;
#pragma unroll
        for (int nf = 0; nf < 8; nf++) {
            int col = bn + wn + nf * 8 + tg * 2;
            float2 bv = *reinterpret_cast<const float2*>(&bias[col]);
            float* a = acc[mf][nf];
            *reinterpret_cast<float2*>(&C[rb0 + col]) = make_float2(a[0] + bv.x, a[1] + bv.y);
            *reinterpret_cast<float2*>(&C[rb1 + col]) = make_float2(a[2] + bv.x, a[3] + bv.y);
        }
    }
}

// ---------------- decoder GEMM: BM=128, BN=256 (validated R13) ------------
#define DTA 10240
#define DTB 20480
#define DSTAGE (2 * DTA + 2 * DTB)
#define GEMMD_SMEM (2 * DSTAGE)

__global__ __launch_bounds__(256, 1) void gemm_dec(
    const __nv_bfloat16* __restrict__ Ahi, const __nv_bfloat16* __restrict__ Alo,
    const __nv_bfloat16* __restrict__ Whi, const __nv_bfloat16* __restrict__ Wlo,
    const float* __restrict__ bias, float* __restrict__ C, int N) {
    extern __shared__ char smdyn[];
    const uint32_t sb = smem_u32(smdyn);
    const int tid  = threadIdx.x;
    const int wid  = tid >> 5;
    const int lane = tid & 31;
    const int bm   = blockIdx.x * 128;
    const int bn   = blockIdx.y * 256;
    const int wm   = (wid & 3) * 32;
    const int wn   = (wid >> 2) * 128;

    float acc[2][16][4];
#pragma unroll
    for (int mf = 0; mf < 2; mf++)
#pragma unroll
        for (int nf = 0; nf < 16; nf++)
#pragma unroll
            for (int r = 0; r < 4; r++) acc[mf][nf][r] = 0.0f;

    const uint32_t a_off = (uint32_t)((wm + (lane & 15)) * SROW + (lane >> 4) * 16);
    const uint32_t b_off = (uint32_t)((wn + (lane & 7) + ((lane >> 4) << 3)) * SROW +
                                      ((lane >> 3) & 1) * 16);

    auto prefetch = [&](int ch, int buf) {
        const int kt = ch * BK;
        const uint32_t base = sb + buf * DSTAGE;
#pragma unroll
        for (int i = 0; i < 12; i++) {
            int id = tid + i * 256;
            int r4 = id >> 2;
            int c4 = id & 3;
            const __nv_bfloat16* src;
            uint32_t dst;
            if (r4 < 256) {
                int sel = r4 >> 7;
                int r   = r4 & 127;
                src = (sel ? Alo : Ahi) + (size_t)(bm + r) * Hz + kt + c4 * 8;
                dst = base + (uint32_t)(sel * DTA) + (uint32_t)(r * SROW + c4 * 16);
            } else {
                int sel = (r4 - 256) >> 8;
                int r   = (r4 - 256) & 255;
                src = (sel ? Wlo : Whi) + (size_t)(bn + r) * Hz + kt + c4 * 8;
                dst = base + 2u * DTA + (uint32_t)(sel * DTB) +
                      (uint32_t)(r * SROW + c4 * 16);
            }
            CPASYNC16(dst, src);
        }
    };

    prefetch(0, 0);
    CPCOMMIT();

    const int NCH = Hz / BK;
    for (int ch = 0; ch < NCH; ch++) {
        const int buf = ch & 1;
        if (ch + 1 < NCH) {
            prefetch(ch + 1, buf ^ 1);
            CPCOMMIT();
            CPWAIT(1);
        } else {
            CPWAIT(0);
        }
        __syncthreads();

        const uint32_t ah_b = sb + buf * DSTAGE;
        const uint32_t al_b = ah_b + DTA;
        const uint32_t wh_b = ah_b + 2 * DTA;
        const uint32_t wl_b = wh_b + DTB;

#pragma unroll
        for (int k16 = 0; k16 < 2; k16++) {
            const uint32_t ko = k16 * 32;
            uint32_t ah[2][4], al[2][4];
#pragma unroll
            for (int mf = 0; mf < 2; mf++) {
                LDSM4(ah[mf], ah_b + a_off + mf * 16 * SROW + ko);
                LDSM4(al[mf], al_b + a_off + mf * 16 * SROW + ko);
            }
#pragma unroll
            for (int half = 0; half < 2; half++) {
                uint32_t bh[4][4], bl[4][4];
#pragma unroll
                for (int j = 0; j < 4; j++) {
                    int nf2 = half * 4 + j;
                    LDSM4(bh[j], wh_b + b_off + nf2 * 16 * SROW + ko);
                    LDSM4(bl[j], wl_b + b_off + nf2 * 16 * SROW + ko);
                }
#pragma unroll
                for (int mf = 0; mf < 2; mf++)
#pragma unroll
                    for (int nfj = 0; nfj < 8; nfj++) {
                        int nf = half * 8 + nfj;
                        uint32_t b0h = bh[nfj >> 1][(nfj & 1) * 2 + 0];
                        uint32_t b1h = bh[nfj >> 1][(nfj & 1) * 2 + 1];
                        uint32_t b0l = bl[nfj >> 1][(nfj & 1) * 2 + 0];
                        uint32_t b1l = bl[nfj >> 1][(nfj & 1) * 2 + 1];
                        MMA16816(acc[mf][nf], ah[mf], b0h, b1h);
                        MMA16816(acc[mf][nf], ah[mf], b0l, b1l);
                        MMA16816(acc[mf][nf], al[mf], b0h, b1h);
                    }
            }
        }
        __syncthreads();
    }

    const int g  = lane >> 2;
    const int tg = lane & 3;
#pragma unroll
    for (int mf = 0; mf < 2; mf++) {
        int m0 = bm + wm + mf * 16 + g;
        int m1 = m0 + 8;
        size_t rb0 = (size_t)((m0 % Bz) * Sz + m0 / Bz) * N;
        size_t rb1 = (size_t)((m1 % Bz) * Sz + m1 / Bz) * N;
#pragma unroll
        for (int nf = 0; nf < 16; nf++) {
            int col = bn + wn + nf * 8 + tg * 2;
            float2 bv = *reinterpret_cast<const float2*>(&bias[col]);
            float* a = acc[mf][nf];
            *reinterpret_cast<float2*>(&C[rb0 + col]) = make_float2(a[0] + bv.x, a[1] + bv.y);
            *reinterpret_cast<float2*>(&C[rb1 + col]) = make_float2(a[2] + bv.x, a[3] + bv.y);
        }
    }
}

// ---------------- persistent LSTM layer kernel (flag arrival + warp-vector poll) ----
// Arrival: per-block flag store at 16B stride (NO same-address atomic serialization).
// Wait: warp 0 only; lane L polls flags of blocks {L, L+32, L+64, L+96}; ~16 L2 lines
// per round per block — light, unlike R12's 16K-thread spin storm.
#define PROWB 2064
#define WH_OFF 0
#define WL_OFF 66048
#define HB_OFF 132096
#define HL_OFF 173376
#define ZR_OFF 214656
#define RD_OFF 216720
#define XP_OFF 224912                    // two 2560B xp buffers
#define BH_OFF 230032
#define CS_OFF 230160
#define PERS_SMEM 230800

__global__ __launch_bounds__(256, 1) void lstm_layer_persistent(
    const __nv_bfloat16* __restrict__ Wph, const __nv_bfloat16* __restrict__ Wpl,
    const float* __restrict__ bh, const float* __restrict__ xp_base,
    __nv_bfloat16* __restrict__ hAh, __nv_bfloat16* __restrict__ hAl,   // [2][32*Hz]
    const float* __restrict__ c_in,
    float* __restrict__ c_final, float* __restrict__ h_final,
    __nv_bfloat16* __restrict__ seq_hi, __nv_bfloat16* __restrict__ seq_lo) {
    extern __shared__ char smdyn[];
    const uint32_t sb = smem_u32(smdyn);
    const int tid  = threadIdx.x;
    const int wid  = tid >> 5;
    const int lane = tid & 31;
    const int blk  = blockIdx.x;
    const int k4   = wid >> 1;
    const int n2   = wid & 1;

    // --- one-time setup: W resident + xp(0) stage, zero row, bias, c state ---
#pragma unroll
    for (int i = 0; i < 32; i++) {
        int c   = tid + i * 256;
        int sel = c >> 12;
        int u   = c & 4095;
        int r   = u >> 7;
        int col = u & 127;
        const __nv_bfloat16* src = (sel ? Wpl : Wph) + (size_t)(blk * 32 + r) * Hz + col * 8;
        CPASYNC16(sb + (sel ? WL_OFF : WH_OFF) + r * PROWB + col * 16, src);
    }
    if (tid < 160) {                      // xp(0) -> buffer 0
        int run = tid >> 1, half = tid & 1;
        const char* src = (const char*)(xp_base + (size_t)(run >> 2) * G4H +
                                        (run & 3) * Hz + blk * 8) + half * 16;
        CPASYNC16(sb + XP_OFF + tid * 16, src);
    }
    CPCOMMIT();
    if (tid < 129)
        *reinterpret_cast<float4*>(smdyn + ZR_OFF + tid * 16) = make_float4(0.f, 0.f, 0.f, 0.f);
    if (tid < 32)
        reinterpret_cast<float*>(smdyn + BH_OFF)[tid] = bh[(tid >> 3) * Hz + blk * 8 + (tid & 7)];
    if (tid < 8 * Bz)
        reinterpret_cast<float*>(smdyn + CS_OFF)[tid] =
            c_in[(tid >> 3) * Hz + blk * 8 + (tid & 7)];
    CPWAIT(0);
    __syncthreads();

    // per-lane invariant ldmatrix offsets
    uint32_t a_row_hi[2], a_row_lo[2];
#pragma unroll
    for (int mf = 0; mf < 2; mf++) {
        int r = mf * 16 + (lane & 15);
        a_row_hi[mf] = (r < Bz) ? (sb + HB_OFF + r * PROWB) : (sb + ZR_OFF);
        a_row_lo[mf] = (r < Bz) ? (sb + HL_OFF + r * PROWB) : (sb + ZR_OFF);
    }
    const uint32_t a_koff0 = (uint32_t)((lane >> 4) * 16);
    const uint32_t b_row = sb + (uint32_t)((n2 * 16 + (lane & 7) + ((lane >> 4) << 3)) * PROWB) +
                           (uint32_t)(((lane >> 3) & 1) * 16);
    float* red = reinterpret_cast<float*>(smdyn + RD_OFF);
    float* bhs = reinterpret_cast<float*>(smdyn + BH_OFF);
    float* cs  = reinterpret_cast<float*>(smdyn + CS_OFF);

    for (int s = 0; s < Sz; s++) {
        const __nv_bfloat16* hih = hAh + (size_t)(s & 1) * 32 * Hz;
        const __nv_bfloat16* hil = hAl + (size_t)(s & 1) * 32 * Hz;
        __nv_bfloat16* hoh = hAh + (size_t)((s + 1) & 1) * 32 * Hz;
        __nv_bfloat16* hol = hAl + (size_t)((s + 1) & 1) * 32 * Hz;

        // issue h loads: 4 k-chunk groups; kc3 also prefetches xp(s+1)
#pragma unroll
        for (int kc = 0; kc < 4; kc++) {
#pragma unroll
            for (int i = 0; i < 5; i++) {
                int c   = tid + i * 256;
                int sel = c >= 640;
                int u   = c - sel * 640;
                int r   = u >> 5;
                int col = u & 31;
                const char* src = (const char*)(sel ? hil : hih) + r * 2048 + kc * 512 + col * 16;
                CPASYNC16(sb + (sel ? HL_OFF : HB_OFF) + r * PROWB + kc * 512 + col * 16, src);
            }
            if (kc == 3 && s + 1 < Sz && tid < 160) {
                const float* xpn = xp_base + (size_t)(s + 1) * Bz * G4H;
                int run = tid >> 1, half = tid & 1;
                const char* src = (const char*)(xpn + (size_t)(run >> 2) * G4H +
                                                (run & 3) * Hz + blk * 8) + half * 16;
                CPASYNC16(sb + XP_OFF + ((s + 1) & 1) * 2560 + tid * 16, src);
            }
            CPCOMMIT();
        }

        float acc[2][2][4];
#pragma unroll
        for (int mf = 0; mf < 2; mf++)
#pragma unroll
            for (int nf = 0; nf < 2; nf++)
#pragma unroll
                for (int r = 0; r < 4; r++) acc[mf][nf][r] = 0.0f;

#pragma unroll
        for (int kc = 0; kc < 4; kc++) {
            if (kc == 0)      CPWAIT(3);
            else if (kc == 1) CPWAIT(2);
            else if (kc == 2) CPWAIT(1);
            else              CPWAIT(0);
            __syncthreads();
#pragma unroll
            for (int ks = 0; ks < 4; ks++) {
                const uint32_t kb = (uint32_t)(kc * 512 + k4 * 128 + ks * 32);
                uint32_t ah[2][4], al[2][4], bhv[4], blv[4];
#pragma unroll
                for (int mf = 0; mf < 2; mf++) {
                    LDSM4(ah[mf], a_row_hi[mf] + a_koff0 + kb);
                    LDSM4(al[mf], a_row_lo[mf] + a_koff0 + kb);
                }
                LDSM4(bhv, b_row + WH_OFF + kb);
                LDSM4(blv, b_row + WL_OFF + kb);
#pragma unroll
                for (int mf = 0; mf < 2; mf++)
#pragma unroll
                    for (int nf = 0; nf < 2; nf++) {
                        uint32_t b0h = bhv[nf * 2], b1h = bhv[nf * 2 + 1];
                        uint32_t b0l = blv[nf * 2], b1l = blv[nf * 2 + 1];
                        MMA16816(acc[mf][nf], ah[mf], b0h, b1h);
                        MMA16816(acc[mf][nf], ah[mf], b0l, b1l);
                        MMA16816(acc[mf][nf], al[mf], b0h, b1h);
                    }
            }
        }

        // two-round k-split reduction into red[2][32][32]
        const int g  = lane >> 2;
        const int tg = lane & 3;
        if (k4 >= 2) {
#pragma unroll
            for (int mf = 0; mf < 2; mf++)
#pragma unroll
                for (int nf = 0; nf < 2; nf++)
#pragma unroll
                    for (int r = 0; r < 4; r++) {
                        int m = g + ((r >> 1) & 1) * 8 + mf * 16;
                        int n = n2 * 16 + nf * 8 + tg * 2 + (r & 1);
                        red[((k4 - 2) * 32 + m) * 32 + n] = acc[mf][nf][r];
                    }
        }
        __syncthreads();
        if (k4 < 2) {
#pragma unroll
            for (int mf = 0; mf < 2; mf++)
#pragma unroll
                for (int nf = 0; nf < 2; nf++)
#pragma unroll
                    for (int r = 0; r < 4; r++) {
                        int m = g + ((r >> 1) & 1) * 8 + mf * 16;
                        int n = n2 * 16 + nf * 8 + tg * 2 + (r & 1);
                        int idx = (k4 * 32 + m) * 32 + n;
                        red[idx] += acc[mf][nf][r];
                    }
        }
        __syncthreads();

        // fused cell update: 8 dims x 20 batches (xp staged LAST step -> buf s&1)
        if (tid < 8 * Bz) {
            float* xps = reinterpret_cast<float*>(smdyn + XP_OFF + (s & 1) * 2560);
            int dl = tid & 7;
            int b  = tid >> 3;
            int d  = blk * 8 + dl;
            float gate[4];
#pragma unroll
            for (int gg = 0; gg < 4; gg++) {
                int n = dl * 4 + gg;
                gate[gg] = red[(0 * 32 + b) * 32 + n] + red[(1 * 32 + b) * 32 + n] +
                           xps[(b * 4 + gg) * 8 + dl] + bhs[gg * 8 + dl];
            }
            float ii = 1.0f / (1.0f + expf(-gate[0]));
            float ff = 1.0f / (1.0f + expf(-gate[1]));
            float gv = tanhf(gate[2]);
            float oo = 1.0f / (1.0f + expf(-gate[3]));
            float cc = cs[tid] * ff + ii * gv;
            float hh = oo * tanhf(cc);
            cs[tid] = cc;
            __nv_bfloat16 bhh = __float2bfloat16(hh);
            __nv_bfloat16 blo = __float2bfloat16(hh - __bfloat162float(bhh));
            hoh[b * Hz + d] = bhh;
            hol[b * Hz + d] = blo;
            seq_hi[(size_t)s * Bz * Hz + b * Hz + d] = bhh;
            seq_lo[(size_t)s * Bz * Hz + b * Hz + d] = blo;
            if (s == Sz - 1) {
                c_final[b * Hz + d] = cc;
                h_final[b * Hz + d] = hh;
            }
        }

        // flag barrier (skip after last step):
        // arrival: fence -> sync -> own-flag store (parallel, no atomic contention)
        // wait: warp 0 polls 128 flags (4 per lane, 16B stride); ~1 L2 round per poll
        if (s < Sz - 1) {
            __threadfence();
            __syncthreads();
            if (tid == 0) {
                volatile int* f = &g_flags[blk * 4];
                *f = s + 1;
            }
            if (wid == 0) {
                bool ok;
                do {
                    int v0 = ((volatile int*)g_flags)[(lane +  0) * 4];
                    int v1 = ((volatile int*)g_flags)[(lane + 32) * 4];
                    int v2 = ((volatile int*)g_flags)[(lane + 64) * 4];
                    int v3 = ((volatile int*)g_flags)[(lane + 96) * 4];
                    int mn = min(min(v0, v1), min(v2, v3));
                    ok = __all_sync(0xffffffffu, mn > s);
                } while (!ok);
            }
            __syncthreads();
        }
    }
}

// ---------------- launch ----------------
extern "C" void kernel_launch(void* const* d_in, const int* in_sizes, int n_in,
                              void* d_out, int out_size) {
    const int*   ids    = (const int*)d_in[0];
    const float* emb    = (const float*)d_in[1];
    const float* x2h_w1 = (const float*)d_in[2];
    const float* x2h_b1 = (const float*)d_in[3];
    const float* h2h_w1 = (const float*)d_in[4];
    const float* h2h_b1 = (const float*)d_in[5];
    const float* x2h_w2 = (const float*)d_in[6];
    const float* x2h_b2 = (const float*)d_in[7];
    const float* h2h_w2 = (const float*)d_in[8];
    const float* h2h_b2 = (const float*)d_in[9];
    const float* dec_w  = (const float*)d_in[10];
    const float* dec_b  = (const float*)d_in[11];
    const float* h01    = (const float*)d_in[12];
    const float* c01    = (const float*)d_in[13];
    const float* h02    = (const float*)d_in[14];
    const float* c02    = (const float*)d_in[15];
    float* out = (float*)d_out;

    float* xproj;
    __nv_bfloat16 *Ahi, *Alo, *w1h, *w1l, *w2h, *w2l, *dwh, *dwl;
    __nv_bfloat16 *hAh, *hAl, *wr1h, *wr1l, *wr2h, *wr2l;
    int* flagp;
    cudaGetSymbolAddress((void**)&xproj, g_xproj);
    cudaGetSymbolAddress((void**)&Ahi, g_A_hi);
    cudaGetSymbolAddress((void**)&Alo, g_A_lo);
    cudaGetSymbolAddress((void**)&w1h, g_w1_hi);
    cudaGetSymbolAddress((void**)&w1l, g_w1_lo);
    cudaGetSymbolAddress((void**)&w2h, g_w2_hi);
    cudaGetSymbolAddress((void**)&w2l, g_w2_lo);
    cudaGetSymbolAddress((void**)&dwh, g_dw_hi);
    cudaGetSymbolAddress((void**)&dwl, g_dw_lo);
    cudaGetSymbolAddress((void**)&hAh, g_hAh);
    cudaGetSymbolAddress((void**)&hAl, g_hAl);
    cudaGetSymbolAddress((void**)&wr1h, g_wr1_hi);
    cudaGetSymbolAddress((void**)&wr1l, g_wr1_lo);
    cudaGetSymbolAddress((void**)&wr2h, g_wr2_hi);
    cudaGetSymbolAddress((void**)&wr2l, g_wr2_lo);
    cudaGetSymbolAddress((void**)&flagp, g_flags);

    cudaFuncSetAttribute(lstm_layer_persistent,
                         cudaFuncAttributeMaxDynamicSharedMemorySize, PERS_SMEM);
    cudaFuncSetAttribute(gemm_mma, cudaFuncAttributeMaxDynamicSharedMemorySize, GEMM_SMEM);
    cudaFuncSetAttribute(gemm_dec, cudaFuncAttributeMaxDynamicSharedMemorySize, GEMMD_SMEM);

    // 0) weight splits
    split_w<<<(G4H * Hz / 4 + 255) / 256, 256>>>(x2h_w1, w1h, w1l, G4H * Hz / 4);
    split_w<<<(G4H * Hz / 4 + 255) / 256, 256>>>(x2h_w2, w2h, w2l, G4H * Hz / 4);
    split_w<<<(Vz * Hz / 4 + 255) / 256, 256>>>(dec_w, dwh, dwl, Vz * Hz / 4);
    perm_split_w<<<G4H, 256>>>(h2h_w1, wr1h, wr1l);
    perm_split_w<<<G4H, 256>>>(h2h_w2, wr2h, wr2l);

    // 1) embedding -> A hi/lo
    embed_split<<<Sz * Bz, 256>>>(ids, emb, Ahi, Alo);

    // 2) x-projection layer 1
    gemm_mma<<<dim3((Sz * Bz) / 128, G4H / 128), 256, GEMM_SMEM>>>(
        Ahi, Alo, w1h, w1l, x2h_b1, xproj, G4H);

    // 3) layer-1 recurrence (persistent)
    float* h1_final = out + (size_t)Bz * Sz * Vz;
    float* c1_final = h1_final + Bz * Hz;
    split_h0<<<20, 256>>>(h01, hAh, hAl);
    cudaMemsetAsync(flagp, 0, 512 * sizeof(int));
    lstm_layer_persistent<<<128, 256, PERS_SMEM>>>(
        wr1h, wr1l, h2h_b1, xproj, hAh, hAl, c01, c1_final, h1_final, Ahi, Alo);

    // 4) x-projection layer 2
    gemm_mma<<<dim3((Sz * Bz) / 128, G4H / 128), 256, GEMM_SMEM>>>(
        Ahi, Alo, w2h, w2l, x2h_b2, xproj, G4H);

    // 5) layer-2 recurrence
    float* h2_final = c1_final + Bz * Hz;
    float* c2_final = h2_final + Bz * Hz;
    split_h0<<<20, 256>>>(h02, hAh, hAl);
    cudaMemsetAsync(flagp, 0, 512 * sizeof(int));
    lstm_layer_persistent<<<128, 256, PERS_SMEM>>>(
        wr2h, wr2l, h2h_b2, xproj, hAh, hAl, c02, c2_final, h2_final, Ahi, Alo);

    // 6) decoder (BM=128 x BN=256)
    gemm_dec<<<dim3((Sz * Bz) / 128, Vz / 256), 256, GEMMD_SMEM>>>(
        Ahi, Alo, dwh, dwl, dec_b, out, Vz);
}

// round 15
// speedup vs baseline: 1.2186x; 1.2186x over previous
#include <cuda_runtime.h>
#include <cuda_bf16.h>
#include <math.h>
#include <stdint.h>

#define Bz 20
#define Sz 256
#define Vz 32000
#define Hz 1024
#define G4H 4096

// ---------------- scratch (static device globals — allocation-free) ----------------
__device__ float g_xproj[Sz * Bz * G4H];                 // [S][B][4H]
__device__ __nv_bfloat16 g_A_hi[Sz * Bz * Hz];           // GEMM A operand (hi)
__device__ __nv_bfloat16 g_A_lo[Sz * Bz * Hz];           // GEMM A operand (lo)
__device__ __nv_bfloat16 g_hAh[2][32 * Hz];              // h state hi (ping-pong)
__device__ __nv_bfloat16 g_hAl[2][32 * Hz];              // h state lo
__device__ __nv_bfloat16 g_w1_hi[G4H * Hz];              // x2h splits
__device__ __nv_bfloat16 g_w1_lo[G4H * Hz];
__device__ __nv_bfloat16 g_w2_hi[G4H * Hz];
__device__ __nv_bfloat16 g_w2_lo[G4H * Hz];
__device__ __nv_bfloat16 g_dw_hi[Vz * Hz];
__device__ __nv_bfloat16 g_dw_lo[Vz * Hz];
__device__ __nv_bfloat16 g_wr1_hi[G4H * Hz];             // h2h permuted splits: row n=d*4+g
__device__ __nv_bfloat16 g_wr1_lo[G4H * Hz];
__device__ __nv_bfloat16 g_wr2_hi[G4H * Hz];
__device__ __nv_bfloat16 g_wr2_lo[G4H * Hz];
__device__ unsigned g_bar;                               // grid barrier counter

// ---------------- PTX helpers (portable) ----------------
__device__ __forceinline__ uint32_t smem_u32(const void* p) {
    uint32_t a;
    asm("{ .reg .u64 t; cvta.to.shared.u64 t, %1; cvt.u32.u64 %0, t; }" : "=r"(a) : "l"(p));
    return a;
}
#define CPASYNC16(dst, src) \
    asm volatile("cp.async.cg.shared.global [%0], [%1], 16;" :: "r"(dst), "l"(src))
#define CPCOMMIT() asm volatile("cp.async.commit_group;" ::: "memory")
#define CPWAIT(n)  asm volatile("cp.async.wait_group %0;" :: "n"(n) : "memory")
#define LDSM4(R, addr)                                                                  \
    asm volatile("ldmatrix.sync.aligned.m8n8.x4.shared.b16 {%0,%1,%2,%3}, [%4];"        \
        : "=r"((R)[0]), "=r"((R)[1]), "=r"((R)[2]), "=r"((R)[3]) : "r"(addr))
#define MMA16816(D, A, B0, B1)                                                          \
    asm volatile("mma.sync.aligned.m16n8k16.row.col.f32.bf16.bf16.f32 "                 \
        "{%0,%1,%2,%3}, {%4,%5,%6,%7}, {%8,%9}, {%0,%1,%2,%3};"                         \
        : "+f"((D)[0]), "+f"((D)[1]), "+f"((D)[2]), "+f"((D)[3])                        \
        : "r"((A)[0]), "r"((A)[1]), "r"((A)[2]), "r"((A)[3]), "r"(B0), "r"(B1))

// ---------------- fp32 -> bf16 hi/lo split helpers ----------------
__device__ __forceinline__ void split4(float4 v, uint2& hi, uint2& lo) {
    float f[4] = {v.x, v.y, v.z, v.w};
    uint32_t h[4], l[4];
#pragma unroll
    for (int i = 0; i < 4; i++) {
        __nv_bfloat16 bh = __float2bfloat16(f[i]);
        __nv_bfloat16 bl = __float2bfloat16(f[i] - __bfloat162float(bh));
        h[i] = __bfloat16_as_ushort(bh);
        l[i] = __bfloat16_as_ushort(bl);
    }
    hi.x = h[0] | (h[1] << 16); hi.y = h[2] | (h[3] << 16);
    lo.x = l[0] | (l[1] << 16); lo.y = l[2] | (l[3] << 16);
}

__global__ void split_w(const float* __restrict__ w, __nv_bfloat16* __restrict__ hi,
                        __nv_bfloat16* __restrict__ lo, int n4) {
    int i = blockIdx.x * 256 + threadIdx.x;
    if (i >= n4) return;
    uint2 h, l;
    split4(reinterpret_cast<const float4*>(w)[i], h, l);
    reinterpret_cast<uint2*>(hi)[i] = h;
    reinterpret_cast<uint2*>(lo)[i] = l;
}

// permuted h2h split: out row n = d*4+g  <-  in row g*1024+d
__global__ void perm_split_w(const float* __restrict__ w, __nv_bfloat16* __restrict__ hi,
                             __nv_bfloat16* __restrict__ lo) {
    int idx = blockIdx.x * 256 + threadIdx.x;
    int n  = idx >> 8;
    int k4 = idx & 255;
    int d = n >> 2, g = n & 3;
    uint2 h, l;
    split4(reinterpret_cast<const float4*>(w)[(g * Hz + d) * 256 + k4], h, l);
    reinterpret_cast<uint2*>(hi)[n * 256 + k4] = h;
    reinterpret_cast<uint2*>(lo)[n * 256 + k4] = l;
}

// split h0 fp32 [20][1024] into hA buffer rows 0..19
__global__ void split_h0(const float* __restrict__ h0, __nv_bfloat16* __restrict__ hi,
                         __nv_bfloat16* __restrict__ lo) {
    int i = blockIdx.x * 256 + threadIdx.x;
    uint2 h, l;
    split4(reinterpret_cast<const float4*>(h0)[i], h, l);
    reinterpret_cast<uint2*>(hi)[i] = h;
    reinterpret_cast<uint2*>(lo)[i] = l;
}

// ---------------- embedding gather -> A hi/lo directly ----------------
__global__ void embed_split(const int* __restrict__ ids, const float* __restrict__ emb,
                            __nv_bfloat16* __restrict__ Ahi, __nv_bfloat16* __restrict__ Alo) {
    int gid = blockIdx.x * 256 + threadIdx.x;
    int c4  = gid & 255;
    int sb  = gid >> 8;
    int b   = sb % Bz;
    int s   = sb / Bz;
    int tok = ids[b * Sz + s];
    float4 v = reinterpret_cast<const float4*>(emb)[(size_t)tok * 256 + c4];
    uint2 h, l;
    split4(v, h, l);
    reinterpret_cast<uint2*>(Ahi)[gid] = h;
    reinterpret_cast<uint2*>(Alo)[gid] = l;
}

// ---------------- HMMA bf16-split GEMM: BM=128, BN=256 (R13-validated structure) ----
// MODE 0: C row-major [M][N].  MODE 1: decoder scatter m=s*B+b -> C[(b*S+s)*N + n].
#define BK 32
#define SROW 80
#define DTA 10240                         // A tile bytes (128 rows * SROW)
#define DTB 20480                         // W tile bytes (256 rows * SROW)
#define DSTAGE (2 * DTA + 2 * DTB)        // 61440 per stage
#define GEMMD_SMEM (2 * DSTAGE)           // 122880

template <int MODE>
__global__ __launch_bounds__(256, 1) void gemm_wide(
    const __nv_bfloat16* __restrict__ Ahi, const __nv_bfloat16* __restrict__ Alo,
    const __nv_bfloat16* __restrict__ Whi, const __nv_bfloat16* __restrict__ Wlo,
    const float* __restrict__ bias, float* __restrict__ C, int N) {
    extern __shared__ char smdyn[];
    const uint32_t sb = smem_u32(smdyn);
    const int tid  = threadIdx.x;
    const int wid  = tid >> 5;
    const int lane = tid & 31;
    const int bm   = blockIdx.x * 128;
    const int bn   = blockIdx.y * 256;
    const int wm   = (wid & 3) * 32;
    const int wn   = (wid >> 2) * 128;

    float acc[2][16][4];
#pragma unroll
    for (int mf = 0; mf < 2; mf++)
#pragma unroll
        for (int nf = 0; nf < 16; nf++)
#pragma unroll
            for (int r = 0; r < 4; r++) acc[mf][nf][r] = 0.0f;

    const uint32_t a_off = (uint32_t)((wm + (lane & 15)) * SROW + (lane >> 4) * 16);
    const uint32_t b_off = (uint32_t)((wn + (lane & 7) + ((lane >> 4) << 3)) * SROW +
                                      ((lane >> 3) & 1) * 16);

    auto prefetch = [&](int ch, int buf) {
        const int kt = ch * BK;
        const uint32_t base = sb + buf * DSTAGE;
#pragma unroll
        for (int i = 0; i < 12; i++) {
            int id = tid + i * 256;               // 0..3071
            int r4 = id >> 2;                     // row 0..767
            int c4 = id & 3;
            const __nv_bfloat16* src;
            uint32_t dst;
            if (r4 < 256) {                       // A hi(0..127) / lo(128..255)
                int sel = r4 >> 7;
                int r   = r4 & 127;
                src = (sel ? Alo : Ahi) + (size_t)(bm + r) * Hz + kt + c4 * 8;
                dst = base + (uint32_t)(sel * DTA) + (uint32_t)(r * SROW + c4 * 16);
            } else {                              // W hi(256..511) / lo(512..767)
                int sel = (r4 - 256) >> 8;
                int r   = (r4 - 256) & 255;
                src = (sel ? Wlo : Whi) + (size_t)(bn + r) * Hz + kt + c4 * 8;
                dst = base + 2u * DTA + (uint32_t)(sel * DTB) +
                      (uint32_t)(r * SROW + c4 * 16);
            }
            CPASYNC16(dst, src);
        }
    };

    prefetch(0, 0);
    CPCOMMIT();

    const int NCH = Hz / BK;                      // 32
    for (int ch = 0; ch < NCH; ch++) {
        const int buf = ch & 1;
        if (ch + 1 < NCH) {
            prefetch(ch + 1, buf ^ 1);
            CPCOMMIT();
            CPWAIT(1);
        } else {
            CPWAIT(0);
        }
        __syncthreads();

        const uint32_t ah_b = sb + buf * DSTAGE;
        const uint32_t al_b = ah_b + DTA;
        const uint32_t wh_b = ah_b + 2 * DTA;
        const uint32_t wl_b = wh_b + DTB;

#pragma unroll
        for (int k16 = 0; k16 < 2; k16++) {
            const uint32_t ko = k16 * 32;
            uint32_t ah[2][4], al[2][4];
#pragma unroll
            for (int mf = 0; mf < 2; mf++) {
                LDSM4(ah[mf], ah_b + a_off + mf * 16 * SROW + ko);
                LDSM4(al[mf], al_b + a_off + mf * 16 * SROW + ko);
            }
#pragma unroll
            for (int half = 0; half < 2; half++) {
                uint32_t bh[4][4], bl[4][4];
#pragma unroll
                for (int j = 0; j < 4; j++) {
                    int nf2 = half * 4 + j;
                    LDSM4(bh[j], wh_b + b_off + nf2 * 16 * SROW + ko);
                    LDSM4(bl[j], wl_b + b_off + nf2 * 16 * SROW + ko);
                }
#pragma unroll
                for (int mf = 0; mf < 2; mf++)
#pragma unroll
                    for (int nfj = 0; nfj < 8; nfj++) {
                        int nf = half * 8 + nfj;
                        uint32_t b0h = bh[nfj >> 1][(nfj & 1) * 2 + 0];
                        uint32_t b1h = bh[nfj >> 1][(nfj & 1) * 2 + 1];
                        uint32_t b0l = bl[nfj >> 1][(nfj & 1) * 2 + 0];
                        uint32_t b1l = bl[nfj >> 1][(nfj & 1) * 2 + 1];
                        MMA16816(acc[mf][nf], ah[mf], b0h, b1h);
                        MMA16816(acc[mf][nf], ah[mf], b0l, b1l);
                        MMA16816(acc[mf][nf], al[mf], b0h, b1h);
                    }
            }
        }
        __syncthreads();
    }

    const int g  = lane >> 2;
    const int tg = lane & 3;
#pragma unroll
    for (int mf = 0; mf < 2; mf++) {
        int m0 = bm + wm + mf * 16 + g;
        int m1 = m0 + 8;
        size_t rb0, rb1;
        if (MODE == 0) {
            rb0 = (size_t)m0 * N;
            rb1 = (size_t)m1 * N;
        } else {
            rb0 = (size_t)((m0 % Bz) * Sz + m0 / Bz) * N;
            rb1 = (size_t)((m1 % Bz) * Sz + m1 / Bz) * N;
        }
#pragma unroll
        for (int nf = 0; nf < 16; nf++) {
            int col = bn + wn + nf * 8 + tg * 2;
            float2 bv = *reinterpret_cast<const float2*>(&bias[col]);
            float* a = acc[mf][nf];
            *reinterpret_cast<float2*>(&C[rb0 + col]) = make_float2(a[0] + bv.x, a[1] + bv.y);
            *reinterpret_cast<float2*>(&C[rb1 + col]) = make_float2(a[2] + bv.x, a[3] + bv.y);
        }
    }
}

// ---------------- persistent LSTM layer kernel (R13: atomic barrier + xp prefetch) --
#define PROWB 2064
#define WH_OFF 0
#define WL_OFF 66048
#define HB_OFF 132096
#define HL_OFF 173376
#define ZR_OFF 214656
#define RD_OFF 216720
#define XP_OFF 224912                    // two 2560B xp buffers
#define BH_OFF 230032
#define CS_OFF 230160
#define PERS_SMEM 230800

__global__ __launch_bounds__(256, 1) void lstm_layer_persistent(
    const __nv_bfloat16* __restrict__ Wph, const __nv_bfloat16* __restrict__ Wpl,
    const float* __restrict__ bh, const float* __restrict__ xp_base,
    __nv_bfloat16* __restrict__ hAh, __nv_bfloat16* __restrict__ hAl,   // [2][32*Hz]
    const float* __restrict__ c_in,
    float* __restrict__ c_final, float* __restrict__ h_final,
    __nv_bfloat16* __restrict__ seq_hi, __nv_bfloat16* __restrict__ seq_lo) {
    extern __shared__ char smdyn[];
    const uint32_t sb = smem_u32(smdyn);
    const int tid  = threadIdx.x;
    const int wid  = tid >> 5;
    const int lane = tid & 31;
    const int blk  = blockIdx.x;
    const int k4   = wid >> 1;
    const int n2   = wid & 1;

    // --- one-time setup: W resident + xp(0) stage, zero row, bias, c state ---
#pragma unroll
    for (int i = 0; i < 32; i++) {
        int c   = tid + i * 256;
        int sel = c >> 12;
        int u   = c & 4095;
        int r   = u >> 7;
        int col = u & 127;
        const __nv_bfloat16* src = (sel ? Wpl : Wph) + (size_t)(blk * 32 + r) * Hz + col * 8;
        CPASYNC16(sb + (sel ? WL_OFF : WH_OFF) + r * PROWB + col * 16, src);
    }
    if (tid < 160) {                      // xp(0) -> buffer 0
        int run = tid >> 1, half = tid & 1;
        const char* src = (const char*)(xp_base + (size_t)(run >> 2) * G4H +
                                        (run & 3) * Hz + blk * 8) + half * 16;
        CPASYNC16(sb + XP_OFF + tid * 16, src);
    }
    CPCOMMIT();
    if (tid < 129)
        *reinterpret_cast<float4*>(smdyn + ZR_OFF + tid * 16) = make_float4(0.f, 0.f, 0.f, 0.f);
    if (tid < 32)
        reinterpret_cast<float*>(smdyn + BH_OFF)[tid] = bh[(tid >> 3) * Hz + blk * 8 + (tid & 7)];
    if (tid < 8 * Bz)
        reinterpret_cast<float*>(smdyn + CS_OFF)[tid] =
            c_in[(tid >> 3) * Hz + blk * 8 + (tid & 7)];
    CPWAIT(0);
    __syncthreads();

    // per-lane invariant ldmatrix offsets
    uint32_t a_row_hi[2], a_row_lo[2];
#pragma unroll
    for (int mf = 0; mf < 2; mf++) {
        int r = mf * 16 + (lane & 15);
        a_row_hi[mf] = (r < Bz) ? (sb + HB_OFF + r * PROWB) : (sb + ZR_OFF);
        a_row_lo[mf] = (r < Bz) ? (sb + HL_OFF + r * PROWB) : (sb + ZR_OFF);
    }
    const uint32_t a_koff0 = (uint32_t)((lane >> 4) * 16);
    const uint32_t b_row = sb + (uint32_t)((n2 * 16 + (lane & 7) + ((lane >> 4) << 3)) * PROWB) +
                           (uint32_t)(((lane >> 3) & 1) * 16);
    float* red = reinterpret_cast<float*>(smdyn + RD_OFF);
    float* bhs = reinterpret_cast<float*>(smdyn + BH_OFF);
    float* cs  = reinterpret_cast<float*>(smdyn + CS_OFF);

    for (int s = 0; s < Sz; s++) {
        const __nv_bfloat16* hih = hAh + (size_t)(s & 1) * 32 * Hz;
        const __nv_bfloat16* hil = hAl + (size_t)(s & 1) * 32 * Hz;
        __nv_bfloat16* hoh = hAh + (size_t)((s + 1) & 1) * 32 * Hz;
        __nv_bfloat16* hol = hAl + (size_t)((s + 1) & 1) * 32 * Hz;

        // issue h loads: 4 k-chunk groups; kc3 also prefetches xp(s+1)
#pragma unroll
        for (int kc = 0; kc < 4; kc++) {
#pragma unroll
            for (int i = 0; i < 5; i++) {
                int c   = tid + i * 256;
                int sel = c >= 640;
                int u   = c - sel * 640;
                int r   = u >> 5;
                int col = u & 31;
                const char* src = (const char*)(sel ? hil : hih) + r * 2048 + kc * 512 + col * 16;
                CPASYNC16(sb + (sel ? HL_OFF : HB_OFF) + r * PROWB + kc * 512 + col * 16, src);
            }
            if (kc == 3 && s + 1 < Sz && tid < 160) {
                const float* xpn = xp_base + (size_t)(s + 1) * Bz * G4H;
                int run = tid >> 1, half = tid & 1;
                const char* src = (const char*)(xpn + (size_t)(run >> 2) * G4H +
                                                (run & 3) * Hz + blk * 8) + half * 16;
                CPASYNC16(sb + XP_OFF + ((s + 1) & 1) * 2560 + tid * 16, src);
            }
            CPCOMMIT();
        }

        float acc[2][2][4];
#pragma unroll
        for (int mf = 0; mf < 2; mf++)
#pragma unroll
            for (int nf = 0; nf < 2; nf++)
#pragma unroll
                for (int r = 0; r < 4; r++) acc[mf][nf][r] = 0.0f;

#pragma unroll
        for (int kc = 0; kc < 4; kc++) {
            if (kc == 0)      CPWAIT(3);
            else if (kc == 1) CPWAIT(2);
            else if (kc == 2) CPWAIT(1);
            else              CPWAIT(0);
            __syncthreads();
#pragma unroll
            for (int ks = 0; ks < 4; ks++) {
                const uint32_t kb = (uint32_t)(kc * 512 + k4 * 128 + ks * 32);
                uint32_t ah[2][4], al[2][4], bhv[4], blv[4];
#pragma unroll
                for (int mf = 0; mf < 2; mf++) {
                    LDSM4(ah[mf], a_row_hi[mf] + a_koff0 + kb);
                    LDSM4(al[mf], a_row_lo[mf] + a_koff0 + kb);
                }
                LDSM4(bhv, b_row + WH_OFF + kb);
                LDSM4(blv, b_row + WL_OFF + kb);
#pragma unroll
                for (int mf = 0; mf < 2; mf++)
#pragma unroll
                    for (int nf = 0; nf < 2; nf++) {
                        uint32_t b0h = bhv[nf * 2], b1h = bhv[nf * 2 + 1];
                        uint32_t b0l = blv[nf * 2], b1l = blv[nf * 2 + 1];
                        MMA16816(acc[mf][nf], ah[mf], b0h, b1h);
                        MMA16816(acc[mf][nf], ah[mf], b0l, b1l);
                        MMA16816(acc[mf][nf], al[mf], b0h, b1h);
                    }
            }
        }

        // two-round k-split reduction into red[2][32][32]
        const int g  = lane >> 2;
        const int tg = lane & 3;
        if (k4 >= 2) {
#pragma unroll
            for (int mf = 0; mf < 2; mf++)
#pragma unroll
                for (int nf = 0; nf < 2; nf++)
#pragma unroll
                    for (int r = 0; r < 4; r++) {
                        int m = g + ((r >> 1) & 1) * 8 + mf * 16;
                        int n = n2 * 16 + nf * 8 + tg * 2 + (r & 1);
                        red[((k4 - 2) * 32 + m) * 32 + n] = acc[mf][nf][r];
                    }
        }
        __syncthreads();
        if (k4 < 2) {
#pragma unroll
            for (int mf = 0; mf < 2; mf++)
#pragma unroll
                for (int nf = 0; nf < 2; nf++)
#pragma unroll
                    for (int r = 0; r < 4; r++) {
                        int m = g + ((r >> 1) & 1) * 8 + mf * 16;
                        int n = n2 * 16 + nf * 8 + tg * 2 + (r & 1);
                        int idx = (k4 * 32 + m) * 32 + n;
                        red[idx] += acc[mf][nf][r];
                    }
        }
        __syncthreads();

        // fused cell update: 8 dims x 20 batches (xp staged LAST step -> buf s&1)
        if (tid < 8 * Bz) {
            float* xps = reinterpret_cast<float*>(smdyn + XP_OFF + (s & 1) * 2560);
            int dl = tid & 7;
            int b  = tid >> 3;
            int d  = blk * 8 + dl;
            float gate[4];
#pragma unroll
            for (int gg = 0; gg < 4; gg++) {
                int n = dl * 4 + gg;
                gate[gg] = red[(0 * 32 + b) * 32 + n] + red[(1 * 32 + b) * 32 + n] +
                           xps[(b * 4 + gg) * 8 + dl] + bhs[gg * 8 + dl];
            }
            float ii = 1.0f / (1.0f + expf(-gate[0]));
            float ff = 1.0f / (1.0f + expf(-gate[1]));
            float gv = tanhf(gate[2]);
            float oo = 1.0f / (1.0f + expf(-gate[3]));
            float cc = cs[tid] * ff + ii * gv;
            float hh = oo * tanhf(cc);
            cs[tid] = cc;
            __nv_bfloat16 bhh = __float2bfloat16(hh);
            __nv_bfloat16 blo = __float2bfloat16(hh - __bfloat162float(bhh));
            hoh[b * Hz + d] = bhh;
            hol[b * Hz + d] = blo;
            seq_hi[(size_t)s * Bz * Hz + b * Hz + d] = bhh;
            seq_lo[(size_t)s * Bz * Hz + b * Hz + d] = blo;
            if (s == Sz - 1) {
                c_final[b * Hz + d] = cc;
                h_final[b * Hz + d] = hh;
            }
        }

        // single grid barrier per step (skip after last) — R13-proven form
        if (s < Sz - 1) {
            __syncthreads();
            if (tid == 0) {
                __threadfence();
                atomicAdd(&g_bar, 1u);
                unsigned target = (unsigned)(s + 1) * (unsigned)gridDim.x;
                volatile unsigned* vb = &g_bar;
                while (*vb < target) {}
            }
            __syncthreads();
        }
    }
}

// ---------------- launch ----------------
extern "C" void kernel_launch(void* const* d_in, const int* in_sizes, int n_in,
                              void* d_out, int out_size) {
    const int*   ids    = (const int*)d_in[0];
    const float* emb    = (const float*)d_in[1];
    const float* x2h_w1 = (const float*)d_in[2];
    const float* x2h_b1 = (const float*)d_in[3];
    const float* h2h_w1 = (const float*)d_in[4];
    const float* h2h_b1 = (const float*)d_in[5];
    const float* x2h_w2 = (const float*)d_in[6];
    const float* x2h_b2 = (const float*)d_in[7];
    const float* h2h_w2 = (const float*)d_in[8];
    const float* h2h_b2 = (const float*)d_in[9];
    const float* dec_w  = (const float*)d_in[10];
    const float* dec_b  = (const float*)d_in[11];
    const float* h01    = (const float*)d_in[12];
    const float* c01    = (const float*)d_in[13];
    const float* h02    = (const float*)d_in[14];
    const float* c02    = (const float*)d_in[15];
    float* out = (float*)d_out;

    float* xproj;
    __nv_bfloat16 *Ahi, *Alo, *w1h, *w1l, *w2h, *w2l, *dwh, *dwl;
    __nv_bfloat16 *hAh, *hAl, *wr1h, *wr1l, *wr2h, *wr2l;
    unsigned* barp;
    cudaGetSymbolAddress((void**)&xproj, g_xproj);
    cudaGetSymbolAddress((void**)&Ahi, g_A_hi);
    cudaGetSymbolAddress((void**)&Alo, g_A_lo);
    cudaGetSymbolAddress((void**)&w1h, g_w1_hi);
    cudaGetSymbolAddress((void**)&w1l, g_w1_lo);
    cudaGetSymbolAddress((void**)&w2h, g_w2_hi);
    cudaGetSymbolAddress((void**)&w2l, g_w2_lo);
    cudaGetSymbolAddress((void**)&dwh, g_dw_hi);
    cudaGetSymbolAddress((void**)&dwl, g_dw_lo);
    cudaGetSymbolAddress((void**)&hAh, g_hAh);
    cudaGetSymbolAddress((void**)&hAl, g_hAl);
    cudaGetSymbolAddress((void**)&wr1h, g_wr1_hi);
    cudaGetSymbolAddress((void**)&wr1l, g_wr1_lo);
    cudaGetSymbolAddress((void**)&wr2h, g_wr2_hi);
    cudaGetSymbolAddress((void**)&wr2l, g_wr2_lo);
    cudaGetSymbolAddress((void**)&barp, g_bar);

    cudaFuncSetAttribute(lstm_layer_persistent,
                         cudaFuncAttributeMaxDynamicSharedMemorySize, PERS_SMEM);
    cudaFuncSetAttribute(gemm_wide<0>, cudaFuncAttributeMaxDynamicSharedMemorySize, GEMMD_SMEM);
    cudaFuncSetAttribute(gemm_wide<1>, cudaFuncAttributeMaxDynamicSharedMemorySize, GEMMD_SMEM);

    // 0) weight splits
    split_w<<<(G4H * Hz / 4 + 255) / 256, 256>>>(x2h_w1, w1h, w1l, G4H * Hz / 4);
    split_w<<<(G4H * Hz / 4 + 255) / 256, 256>>>(x2h_w2, w2h, w2l, G4H * Hz / 4);
    split_w<<<(Vz * Hz / 4 + 255) / 256, 256>>>(dec_w, dwh, dwl, Vz * Hz / 4);
    perm_split_w<<<G4H, 256>>>(h2h_w1, wr1h, wr1l);
    perm_split_w<<<G4H, 256>>>(h2h_w2, wr2h, wr2l);

    // 1) embedding -> A hi/lo
    embed_split<<<Sz * Bz, 256>>>(ids, emb, Ahi, Alo);

    // 2) x-projection layer 1 (BM=128 x BN=256, row-major epilogue)
    gemm_wide<0><<<dim3((Sz * Bz) / 128, G4H / 256), 256, GEMMD_SMEM>>>(
        Ahi, Alo, w1h, w1l, x2h_b1, xproj, G4H);

    // 3) layer-1 recurrence (persistent)
    float* h1_final = out + (size_t)Bz * Sz * Vz;
    float* c1_final = h1_final + Bz * Hz;
    split_h0<<<20, 256>>>(h01, hAh, hAl);
    cudaMemsetAsync(barp, 0, sizeof(unsigned));
    lstm_layer_persistent<<<128, 256, PERS_SMEM>>>(
        wr1h, wr1l, h2h_b1, xproj, hAh, hAl, c01, c1_final, h1_final, Ahi, Alo);

    // 4) x-projection layer 2
    gemm_wide<0><<<dim3((Sz * Bz) / 128, G4H / 256), 256, GEMMD_SMEM>>>(
        Ahi, Alo, w2h, w2l, x2h_b2, xproj, G4H);

    // 5) layer-2 recurrence
    float* h2_final = c1_final + Bz * Hz;
    float* c2_final = h2_final + Bz * Hz;
    split_h0<<<20, 256>>>(h02, hAh, hAl);
    cudaMemsetAsync(barp, 0, sizeof(unsigned));
    lstm_layer_persistent<<<128, 256, PERS_SMEM>>>(
        wr2h, wr2l, h2h_b2, xproj, hAh, hAl, c02, c2_final, h2_final, Ahi, Alo);

    // 6) decoder (BM=128 x BN=256, scatter epilogue)
    gemm_wide<1><<<dim3((Sz * Bz) / 128, Vz / 256), 256, GEMMD_SMEM>>>(
        Ahi, Alo, dwh, dwl, dec_b, out, Vz);
}

// round 16
// speedup vs baseline: 1.2198x; 1.0010x over previous
#include <cuda_runtime.h>
#include <cuda_bf16.h>
#include <math.h>
#include <stdint.h>

#define Bz 20
#define Sz 256
#define Vz 32000
#define Hz 1024
#define G4H 4096

// ---------------- scratch (static device globals — allocation-free) ----------------
__device__ float g_xproj[Sz * Bz * G4H];                 // [S][B][4H]
__device__ __nv_bfloat16 g_A_hi[Sz * Bz * Hz];           // GEMM A operand (hi)
__device__ __nv_bfloat16 g_A_lo[Sz * Bz * Hz];           // GEMM A operand (lo)
__device__ __nv_bfloat16 g_hAh[2][32 * Hz];              // h state hi (ping-pong)
__device__ __nv_bfloat16 g_hAl[2][32 * Hz];              // h state lo
__device__ __nv_bfloat16 g_w1_hi[G4H * Hz];              // x2h splits
__device__ __nv_bfloat16 g_w1_lo[G4H * Hz];
__device__ __nv_bfloat16 g_w2_hi[G4H * Hz];
__device__ __nv_bfloat16 g_w2_lo[G4H * Hz];
__device__ __nv_bfloat16 g_dw_hi[Vz * Hz];
__device__ __nv_bfloat16 g_dw_lo[Vz * Hz];
__device__ __nv_bfloat16 g_wr1_hi[G4H * Hz];             // h2h permuted splits: row n=d*4+g
__device__ __nv_bfloat16 g_wr1_lo[G4H * Hz];
__device__ __nv_bfloat16 g_wr2_hi[G4H * Hz];
__device__ __nv_bfloat16 g_wr2_lo[G4H * Hz];
__device__ unsigned g_bar;                               // grid barrier counter

// ---------------- PTX helpers (portable) ----------------
__device__ __forceinline__ uint32_t smem_u32(const void* p) {
    uint32_t a;
    asm("{ .reg .u64 t; cvta.to.shared.u64 t, %1; cvt.u32.u64 %0, t; }" : "=r"(a) : "l"(p));
    return a;
}
#define CPASYNC16(dst, src) \
    asm volatile("cp.async.cg.shared.global [%0], [%1], 16;" :: "r"(dst), "l"(src))
#define CPCOMMIT() asm volatile("cp.async.commit_group;" ::: "memory")
#define CPWAIT(n)  asm volatile("cp.async.wait_group %0;" :: "n"(n) : "memory")
#define LDSM4(R, addr)                                                                  \
    asm volatile("ldmatrix.sync.aligned.m8n8.x4.shared.b16 {%0,%1,%2,%3}, [%4];"        \
        : "=r"((R)[0]), "=r"((R)[1]), "=r"((R)[2]), "=r"((R)[3]) : "r"(addr))
#define MMA16816(D, A, B0, B1)                                                          \
    asm volatile("mma.sync.aligned.m16n8k16.row.col.f32.bf16.bf16.f32 "                 \
        "{%0,%1,%2,%3}, {%4,%5,%6,%7}, {%8,%9}, {%0,%1,%2,%3};"                         \
        : "+f"((D)[0]), "+f"((D)[1]), "+f"((D)[2]), "+f"((D)[3])                        \
        : "r"((A)[0]), "r"((A)[1]), "r"((A)[2]), "r"((A)[3]), "r"(B0), "r"(B1))

// ---------------- fp32 -> bf16 hi/lo split helpers ----------------
__device__ __forceinline__ void split4(float4 v, uint2& hi, uint2& lo) {
    float f[4] = {v.x, v.y, v.z, v.w};
    uint32_t h[4], l[4];
#pragma unroll
    for (int i = 0; i < 4; i++) {
        __nv_bfloat16 bh = __float2bfloat16(f[i]);
        __nv_bfloat16 bl = __float2bfloat16(f[i] - __bfloat162float(bh));
        h[i] = __bfloat16_as_ushort(bh);
        l[i] = __bfloat16_as_ushort(bl);
    }
    hi.x = h[0] | (h[1] << 16); hi.y = h[2] | (h[3] << 16);
    lo.x = l[0] | (l[1] << 16); lo.y = l[2] | (l[3] << 16);
}

__global__ void split_w(const float* __restrict__ w, __nv_bfloat16* __restrict__ hi,
                        __nv_bfloat16* __restrict__ lo, int n4) {
    int i = blockIdx.x * 256 + threadIdx.x;
    if (i >= n4) return;
    uint2 h, l;
    split4(reinterpret_cast<const float4*>(w)[i], h, l);
    reinterpret_cast<uint2*>(hi)[i] = h;
    reinterpret_cast<uint2*>(lo)[i] = l;
}

// permuted h2h split: out row n = d*4+g  <-  in row g*1024+d
__global__ void perm_split_w(const float* __restrict__ w, __nv_bfloat16* __restrict__ hi,
                             __nv_bfloat16* __restrict__ lo) {
    int idx = blockIdx.x * 256 + threadIdx.x;
    int n  = idx >> 8;
    int k4 = idx & 255;
    int d = n >> 2, g = n & 3;
    uint2 h, l;
    split4(reinterpret_cast<const float4*>(w)[(g * Hz + d) * 256 + k4], h, l);
    reinterpret_cast<uint2*>(hi)[n * 256 + k4] = h;
    reinterpret_cast<uint2*>(lo)[n * 256 + k4] = l;
}

// split h0 fp32 [20][1024] into hA buffer rows 0..19; also clears the grid barrier
// (kernel-boundary ordering makes the clear visible to the following lstm launch).
__global__ void split_h0(const float* __restrict__ h0, __nv_bfloat16* __restrict__ hi,
                         __nv_bfloat16* __restrict__ lo) {
    if (blockIdx.x == 0 && threadIdx.x == 0) g_bar = 0u;
    int i = blockIdx.x * 256 + threadIdx.x;
    uint2 h, l;
    split4(reinterpret_cast<const float4*>(h0)[i], h, l);
    reinterpret_cast<uint2*>(hi)[i] = h;
    reinterpret_cast<uint2*>(lo)[i] = l;
}

// ---------------- embedding gather -> A hi/lo directly ----------------
__global__ void embed_split(const int* __restrict__ ids, const float* __restrict__ emb,
                            __nv_bfloat16* __restrict__ Ahi, __nv_bfloat16* __restrict__ Alo) {
    int gid = blockIdx.x * 256 + threadIdx.x;
    int c4  = gid & 255;
    int sb  = gid >> 8;
    int b   = sb % Bz;
    int s   = sb / Bz;
    int tok = ids[b * Sz + s];
    float4 v = reinterpret_cast<const float4*>(emb)[(size_t)tok * 256 + c4];
    uint2 h, l;
    split4(v, h, l);
    reinterpret_cast<uint2*>(Ahi)[gid] = h;
    reinterpret_cast<uint2*>(Alo)[gid] = l;
}

// ---------------- HMMA bf16-split GEMM: BM=128, BN=256 (validated) ----------------
// MODE 0: C row-major [M][N].  MODE 1: decoder scatter m=s*B+b -> C[(b*S+s)*N + n].
#define BK 32
#define SROW 80
#define DTA 10240                         // A tile bytes (128 rows * SROW)
#define DTB 20480                         // W tile bytes (256 rows * SROW)
#define DSTAGE (2 * DTA + 2 * DTB)        // 61440 per stage
#define GEMMD_SMEM (2 * DSTAGE)           // 122880

template <int MODE>
__global__ __launch_bounds__(256, 1) void gemm_wide(
    const __nv_bfloat16* __restrict__ Ahi, const __nv_bfloat16* __restrict__ Alo,
    const __nv_bfloat16* __restrict__ Whi, const __nv_bfloat16* __restrict__ Wlo,
    const float* __restrict__ bias, float* __restrict__ C, int N) {
    extern __shared__ char smdyn[];
    const uint32_t sb = smem_u32(smdyn);
    const int tid  = threadIdx.x;
    const int wid  = tid >> 5;
    const int lane = tid & 31;
    const int bm   = blockIdx.x * 128;
    const int bn   = blockIdx.y * 256;
    const int wm   = (wid & 3) * 32;
    const int wn   = (wid >> 2) * 128;

    float acc[2][16][4];
#pragma unroll
    for (int mf = 0; mf < 2; mf++)
#pragma unroll
        for (int nf = 0; nf < 16; nf++)
#pragma unroll
            for (int r = 0; r < 4; r++) acc[mf][nf][r] = 0.0f;

    const uint32_t a_off = (uint32_t)((wm + (lane & 15)) * SROW + (lane >> 4) * 16);
    const uint32_t b_off = (uint32_t)((wn + (lane & 7) + ((lane >> 4) << 3)) * SROW +
                                      ((lane >> 3) & 1) * 16);

    auto prefetch = [&](int ch, int buf) {
        const int kt = ch * BK;
        const uint32_t base = sb + buf * DSTAGE;
#pragma unroll
        for (int i = 0; i < 12; i++) {
            int id = tid + i * 256;               // 0..3071
            int r4 = id >> 2;                     // row 0..767
            int c4 = id & 3;
            const __nv_bfloat16* src;
            uint32_t dst;
            if (r4 < 256) {                       // A hi(0..127) / lo(128..255)
                int sel = r4 >> 7;
                int r   = r4 & 127;
                src = (sel ? Alo : Ahi) + (size_t)(bm + r) * Hz + kt + c4 * 8;
                dst = base + (uint32_t)(sel * DTA) + (uint32_t)(r * SROW + c4 * 16);
            } else {                              // W hi(256..511) / lo(512..767)
                int sel = (r4 - 256) >> 8;
                int r   = (r4 - 256) & 255;
                src = (sel ? Wlo : Whi) + (size_t)(bn + r) * Hz + kt + c4 * 8;
                dst = base + 2u * DTA + (uint32_t)(sel * DTB) +
                      (uint32_t)(r * SROW + c4 * 16);
            }
            CPASYNC16(dst, src);
        }
    };

    prefetch(0, 0);
    CPCOMMIT();

    const int NCH = Hz / BK;                      // 32
    for (int ch = 0; ch < NCH; ch++) {
        const int buf = ch & 1;
        if (ch + 1 < NCH) {
            prefetch(ch + 1, buf ^ 1);
            CPCOMMIT();
            CPWAIT(1);
        } else {
            CPWAIT(0);
        }
        __syncthreads();

        const uint32_t ah_b = sb + buf * DSTAGE;
        const uint32_t al_b = ah_b + DTA;
        const uint32_t wh_b = ah_b + 2 * DTA;
        const uint32_t wl_b = wh_b + DTB;

#pragma unroll
        for (int k16 = 0; k16 < 2; k16++) {
            const uint32_t ko = k16 * 32;
            uint32_t ah[2][4], al[2][4];
#pragma unroll
            for (int mf = 0; mf < 2; mf++) {
                LDSM4(ah[mf], ah_b + a_off + mf * 16 * SROW + ko);
                LDSM4(al[mf], al_b + a_off + mf * 16 * SROW + ko);
            }
#pragma unroll
            for (int half = 0; half < 2; half++) {
                uint32_t bh[4][4], bl[4][4];
#pragma unroll
                for (int j = 0; j < 4; j++) {
                    int nf2 = half * 4 + j;
                    LDSM4(bh[j], wh_b + b_off + nf2 * 16 * SROW + ko);
                    LDSM4(bl[j], wl_b + b_off + nf2 * 16 * SROW + ko);
                }
#pragma unroll
                for (int mf = 0; mf < 2; mf++)
#pragma unroll
                    for (int nfj = 0; nfj < 8; nfj++) {
                        int nf = half * 8 + nfj;
                        uint32_t b0h = bh[nfj >> 1][(nfj & 1) * 2 + 0];
                        uint32_t b1h = bh[nfj >> 1][(nfj & 1) * 2 + 1];
                        uint32_t b0l = bl[nfj >> 1][(nfj & 1) * 2 + 0];
                        uint32_t b1l = bl[nfj >> 1][(nfj & 1) * 2 + 1];
                        MMA16816(acc[mf][nf], ah[mf], b0h, b1h);
                        MMA16816(acc[mf][nf], ah[mf], b0l, b1l);
                        MMA16816(acc[mf][nf], al[mf], b0h, b1h);
                    }
            }
        }
        __syncthreads();
    }

    const int g  = lane >> 2;
    const int tg = lane & 3;
#pragma unroll
    for (int mf = 0; mf < 2; mf++) {
        int m0 = bm + wm + mf * 16 + g;
        int m1 = m0 + 8;
        size_t rb0, rb1;
        if (MODE == 0) {
            rb0 = (size_t)m0 * N;
            rb1 = (size_t)m1 * N;
        } else {
            rb0 = (size_t)((m0 % Bz) * Sz + m0 / Bz) * N;
            rb1 = (size_t)((m1 % Bz) * Sz + m1 / Bz) * N;
        }
#pragma unroll
        for (int nf = 0; nf < 16; nf++) {
            int col = bn + wn + nf * 8 + tg * 2;
            float2 bv = *reinterpret_cast<const float2*>(&bias[col]);
            float* a = acc[mf][nf];
            *reinterpret_cast<float2*>(&C[rb0 + col]) = make_float2(a[0] + bv.x, a[1] + bv.y);
            *reinterpret_cast<float2*>(&C[rb1 + col]) = make_float2(a[2] + bv.x, a[3] + bv.y);
        }
    }
}

// ---------------- persistent LSTM layer kernel (R13: atomic barrier + xp prefetch) --
#define PROWB 2064
#define WH_OFF 0
#define WL_OFF 66048
#define HB_OFF 132096
#define HL_OFF 173376
#define ZR_OFF 214656
#define RD_OFF 216720
#define XP_OFF 224912                    // two 2560B xp buffers
#define BH_OFF 230032
#define CS_OFF 230160
#define PERS_SMEM 230800

__global__ __launch_bounds__(256, 1) void lstm_layer_persistent(
    const __nv_bfloat16* __restrict__ Wph, const __nv_bfloat16* __restrict__ Wpl,
    const float* __restrict__ bh, const float* __restrict__ xp_base,
    __nv_bfloat16* __restrict__ hAh, __nv_bfloat16* __restrict__ hAl,   // [2][32*Hz]
    const float* __restrict__ c_in,
    float* __restrict__ c_final, float* __restrict__ h_final,
    __nv_bfloat16* __restrict__ seq_hi, __nv_bfloat16* __restrict__ seq_lo) {
    extern __shared__ char smdyn[];
    const uint32_t sb = smem_u32(smdyn);
    const int tid  = threadIdx.x;
    const int wid  = tid >> 5;
    const int lane = tid & 31;
    const int blk  = blockIdx.x;
    const int k4   = wid >> 1;
    const int n2   = wid & 1;

    // --- one-time setup: W resident + xp(0) stage, zero row, bias, c state ---
#pragma unroll
    for (int i = 0; i < 32; i++) {
        int c   = tid + i * 256;
        int sel = c >> 12;
        int u   = c & 4095;
        int r   = u >> 7;
        int col = u & 127;
        const __nv_bfloat16* src = (sel ? Wpl : Wph) + (size_t)(blk * 32 + r) * Hz + col * 8;
        CPASYNC16(sb + (sel ? WL_OFF : WH_OFF) + r * PROWB + col * 16, src);
    }
    if (tid < 160) {                      // xp(0) -> buffer 0
        int run = tid >> 1, half = tid & 1;
        const char* src = (const char*)(xp_base + (size_t)(run >> 2) * G4H +
                                        (run & 3) * Hz + blk * 8) + half * 16;
        CPASYNC16(sb + XP_OFF + tid * 16, src);
    }
    CPCOMMIT();
    if (tid < 129)
        *reinterpret_cast<float4*>(smdyn + ZR_OFF + tid * 16) = make_float4(0.f, 0.f, 0.f, 0.f);
    if (tid < 32)
        reinterpret_cast<float*>(smdyn + BH_OFF)[tid] = bh[(tid >> 3) * Hz + blk * 8 + (tid & 7)];
    if (tid < 8 * Bz)
        reinterpret_cast<float*>(smdyn + CS_OFF)[tid] =
            c_in[(tid >> 3) * Hz + blk * 8 + (tid & 7)];
    CPWAIT(0);
    __syncthreads();

    // per-lane invariant ldmatrix offsets
    uint32_t a_row_hi[2], a_row_lo[2];
#pragma unroll
    for (int mf = 0; mf < 2; mf++) {
        int r = mf * 16 + (lane & 15);
        a_row_hi[mf] = (r < Bz) ? (sb + HB_OFF + r * PROWB) : (sb + ZR_OFF);
        a_row_lo[mf] = (r < Bz) ? (sb + HL_OFF + r * PROWB) : (sb + ZR_OFF);
    }
    const uint32_t a_koff0 = (uint32_t)((lane >> 4) * 16);
    const uint32_t b_row = sb + (uint32_t)((n2 * 16 + (lane & 7) + ((lane >> 4) << 3)) * PROWB) +
                           (uint32_t)(((lane >> 3) & 1) * 16);
    float* red = reinterpret_cast<float*>(smdyn + RD_OFF);
    float* bhs = reinterpret_cast<float*>(smdyn + BH_OFF);
    float* cs  = reinterpret_cast<float*>(smdyn + CS_OFF);

    for (int s = 0; s < Sz; s++) {
        const __nv_bfloat16* hih = hAh + (size_t)(s & 1) * 32 * Hz;
        const __nv_bfloat16* hil = hAl + (size_t)(s & 1) * 32 * Hz;
        __nv_bfloat16* hoh = hAh + (size_t)((s + 1) & 1) * 32 * Hz;
        __nv_bfloat16* hol = hAl + (size_t)((s + 1) & 1) * 32 * Hz;

        // issue h loads: 4 k-chunk groups; kc3 also prefetches xp(s+1)
#pragma unroll
        for (int kc = 0; kc < 4; kc++) {
#pragma unroll
            for (int i = 0; i < 5; i++) {
                int c   = tid + i * 256;
                int sel = c >= 640;
                int u   = c - sel * 640;
                int r   = u >> 5;
                int col = u & 31;
                const char* src = (const char*)(sel ? hil : hih) + r * 2048 + kc * 512 + col * 16;
                CPASYNC16(sb + (sel ? HL_OFF : HB_OFF) + r * PROWB + kc * 512 + col * 16, src);
            }
            if (kc == 3 && s + 1 < Sz && tid < 160) {
                const float* xpn = xp_base + (size_t)(s + 1) * Bz * G4H;
                int run = tid >> 1, half = tid & 1;
                const char* src = (const char*)(xpn + (size_t)(run >> 2) * G4H +
                                                (run & 3) * Hz + blk * 8) + half * 16;
                CPASYNC16(sb + XP_OFF + ((s + 1) & 1) * 2560 + tid * 16, src);
            }
            CPCOMMIT();
        }

        float acc[2][2][4];
#pragma unroll
        for (int mf = 0; mf < 2; mf++)
#pragma unroll
            for (int nf = 0; nf < 2; nf++)
#pragma unroll
                for (int r = 0; r < 4; r++) acc[mf][nf][r] = 0.0f;

#pragma unroll
        for (int kc = 0; kc < 4; kc++) {
            if (kc == 0)      CPWAIT(3);
            else if (kc == 1) CPWAIT(2);
            else if (kc == 2) CPWAIT(1);
            else              CPWAIT(0);
            __syncthreads();
#pragma unroll
            for (int ks = 0; ks < 4; ks++) {
                const uint32_t kb = (uint32_t)(kc * 512 + k4 * 128 + ks * 32);
                uint32_t ah[2][4], al[2][4], bhv[4], blv[4];
#pragma unroll
                for (int mf = 0; mf < 2; mf++) {
                    LDSM4(ah[mf], a_row_hi[mf] + a_koff0 + kb);
                    LDSM4(al[mf], a_row_lo[mf] + a_koff0 + kb);
                }
                LDSM4(bhv, b_row + WH_OFF + kb);
                LDSM4(blv, b_row + WL_OFF + kb);
#pragma unroll
                for (int mf = 0; mf < 2; mf++)
#pragma unroll
                    for (int nf = 0; nf < 2; nf++) {
                        uint32_t b0h = bhv[nf * 2], b1h = bhv[nf * 2 + 1];
                        uint32_t b0l = blv[nf * 2], b1l = blv[nf * 2 + 1];
                        MMA16816(acc[mf][nf], ah[mf], b0h, b1h);
                        MMA16816(acc[mf][nf], ah[mf], b0l, b1l);
                        MMA16816(acc[mf][nf], al[mf], b0h, b1h);
                    }
            }
        }

        // two-round k-split reduction into red[2][32][32]
        const int g  = lane >> 2;
        const int tg = lane & 3;
        if (k4 >= 2) {
#pragma unroll
            for (int mf = 0; mf < 2; mf++)
#pragma unroll
                for (int nf = 0; nf < 2; nf++)
#pragma unroll
                    for (int r = 0; r < 4; r++) {
                        int m = g + ((r >> 1) & 1) * 8 + mf * 16;
                        int n = n2 * 16 + nf * 8 + tg * 2 + (r & 1);
                        red[((k4 - 2) * 32 + m) * 32 + n] = acc[mf][nf][r];
                    }
        }
        __syncthreads();
        if (k4 < 2) {
#pragma unroll
            for (int mf = 0; mf < 2; mf++)
#pragma unroll
                for (int nf = 0; nf < 2; nf++)
#pragma unroll
                    for (int r = 0; r < 4; r++) {
                        int m = g + ((r >> 1) & 1) * 8 + mf * 16;
                        int n = n2 * 16 + nf * 8 + tg * 2 + (r & 1);
                        int idx = (k4 * 32 + m) * 32 + n;
                        red[idx] += acc[mf][nf][r];
                    }
        }
        __syncthreads();

        // fused cell update: 8 dims x 20 batches (xp staged LAST step -> buf s&1)
        if (tid < 8 * Bz) {
            float* xps = reinterpret_cast<float*>(smdyn + XP_OFF + (s & 1) * 2560);
            int dl = tid & 7;
            int b  = tid >> 3;
            int d  = blk * 8 + dl;
            float gate[4];
#pragma unroll
            for (int gg = 0; gg < 4; gg++) {
                int n = dl * 4 + gg;
                gate[gg] = red[(0 * 32 + b) * 32 + n] + red[(1 * 32 + b) * 32 + n] +
                           xps[(b * 4 + gg) * 8 + dl] + bhs[gg * 8 + dl];
            }
            float ii = 1.0f / (1.0f + expf(-gate[0]));
            float ff = 1.0f / (1.0f + expf(-gate[1]));
            float gv = tanhf(gate[2]);
            float oo = 1.0f / (1.0f + expf(-gate[3]));
            float cc = cs[tid] * ff + ii * gv;
            float hh = oo * tanhf(cc);
            cs[tid] = cc;
            __nv_bfloat16 bhh = __float2bfloat16(hh);
            __nv_bfloat16 blo = __float2bfloat16(hh - __bfloat162float(bhh));
            hoh[b * Hz + d] = bhh;
            hol[b * Hz + d] = blo;
            seq_hi[(size_t)s * Bz * Hz + b * Hz + d] = bhh;
            seq_lo[(size_t)s * Bz * Hz + b * Hz + d] = blo;
            if (s == Sz - 1) {
                c_final[b * Hz + d] = cc;
                h_final[b * Hz + d] = hh;
            }
        }

        // single grid barrier per step (skip after last) — R13-proven form
        if (s < Sz - 1) {
            __syncthreads();
            if (tid == 0) {
                __threadfence();
                atomicAdd(&g_bar, 1u);
                unsigned target = (unsigned)(s + 1) * (unsigned)gridDim.x;
                volatile unsigned* vb = &g_bar;
                while (*vb < target) {}
            }
            __syncthreads();
        }
    }
}

// ---------------- launch ----------------
// Launch order engineered so lstm_layer_persistent (layer 1) is the 6th kernel
// launch — the ncu capture window (-s 5 -c 1) then profiles IT instead of a
// split kernel. Deferred kernels (w2/dec splits) have no dependency before
// their new position; single-stream total work is identical.
extern "C" void kernel_launch(void* const* d_in, const int* in_sizes, int n_in,
                              void* d_out, int out_size) {
    const int*   ids    = (const int*)d_in[0];
    const float* emb    = (const float*)d_in[1];
    const float* x2h_w1 = (const float*)d_in[2];
    const float* x2h_b1 = (const float*)d_in[3];
    const float* h2h_w1 = (const float*)d_in[4];
    const float* h2h_b1 = (const float*)d_in[5];
    const float* x2h_w2 = (const float*)d_in[6];
    const float* x2h_b2 = (const float*)d_in[7];
    const float* h2h_w2 = (const float*)d_in[8];
    const float* h2h_b2 = (const float*)d_in[9];
    const float* dec_w  = (const float*)d_in[10];
    const float* dec_b  = (const float*)d_in[11];
    const float* h01    = (const float*)d_in[12];
    const float* c01    = (const float*)d_in[13];
    const float* h02    = (const float*)d_in[14];
    const float* c02    = (const float*)d_in[15];
    float* out = (float*)d_out;

    float* xproj;
    __nv_bfloat16 *Ahi, *Alo, *w1h, *w1l, *w2h, *w2l, *dwh, *dwl;
    __nv_bfloat16 *hAh, *hAl, *wr1h, *wr1l, *wr2h, *wr2l;
    cudaGetSymbolAddress((void**)&xproj, g_xproj);
    cudaGetSymbolAddress((void**)&Ahi, g_A_hi);
    cudaGetSymbolAddress((void**)&Alo, g_A_lo);
    cudaGetSymbolAddress((void**)&w1h, g_w1_hi);
    cudaGetSymbolAddress((void**)&w1l, g_w1_lo);
    cudaGetSymbolAddress((void**)&w2h, g_w2_hi);
    cudaGetSymbolAddress((void**)&w2l, g_w2_lo);
    cudaGetSymbolAddress((void**)&dwh, g_dw_hi);
    cudaGetSymbolAddress((void**)&dwl, g_dw_lo);
    cudaGetSymbolAddress((void**)&hAh, g_hAh);
    cudaGetSymbolAddress((void**)&hAl, g_hAl);
    cudaGetSymbolAddress((void**)&wr1h, g_wr1_hi);
    cudaGetSymbolAddress((void**)&wr1l, g_wr1_lo);
    cudaGetSymbolAddress((void**)&wr2h, g_wr2_hi);
    cudaGetSymbolAddress((void**)&wr2l, g_wr2_lo);

    cudaFuncSetAttribute(lstm_layer_persistent,
                         cudaFuncAttributeMaxDynamicSharedMemorySize, PERS_SMEM);
    cudaFuncSetAttribute(gemm_wide<0>, cudaFuncAttributeMaxDynamicSharedMemorySize, GEMMD_SMEM);
    cudaFuncSetAttribute(gemm_wide<1>, cudaFuncAttributeMaxDynamicSharedMemorySize, GEMMD_SMEM);

    float* h1_final = out + (size_t)Bz * Sz * Vz;
    float* c1_final = h1_final + Bz * Hz;
    float* h2_final = c1_final + Bz * Hz;
    float* c2_final = h2_final + Bz * Hz;

    // #0 layer-1 x2h split
    split_w<<<(G4H * Hz / 4 + 255) / 256, 256>>>(x2h_w1, w1h, w1l, G4H * Hz / 4);
    // #1 layer-1 h2h permuted split
    perm_split_w<<<G4H, 256>>>(h2h_w1, wr1h, wr1l);
    // #2 embedding -> A hi/lo
    embed_split<<<Sz * Bz, 256>>>(ids, emb, Ahi, Alo);
    // #3 x-projection layer 1
    gemm_wide<0><<<dim3((Sz * Bz) / 128, G4H / 256), 256, GEMMD_SMEM>>>(
        Ahi, Alo, w1h, w1l, x2h_b1, xproj, G4H);
    // #4 h0 split (also clears g_bar)
    split_h0<<<20, 256>>>(h01, hAh, hAl);
    // #5 layer-1 recurrence  <-- ncu -s 5 -c 1 captures this launch
    lstm_layer_persistent<<<128, 256, PERS_SMEM>>>(
        wr1h, wr1l, h2h_b1, xproj, hAh, hAl, c01, c1_final, h1_final, Ahi, Alo);

    // deferred prep for layer 2 / decoder
    split_w<<<(G4H * Hz / 4 + 255) / 256, 256>>>(x2h_w2, w2h, w2l, G4H * Hz / 4);
    perm_split_w<<<G4H, 256>>>(h2h_w2, wr2h, wr2l);
    split_w<<<(Vz * Hz / 4 + 255) / 256, 256>>>(dec_w, dwh, dwl, Vz * Hz / 4);

    // x-projection layer 2
    gemm_wide<0><<<dim3((Sz * Bz) / 128, G4H / 256), 256, GEMMD_SMEM>>>(
        Ahi, Alo, w2h, w2l, x2h_b2, xproj, G4H);

    // layer-2 recurrence
    split_h0<<<20, 256>>>(h02, hAh, hAl);
    lstm_layer_persistent<<<128, 256, PERS_SMEM>>>(
        wr2h, wr2l, h2h_b2, xproj, hAh, hAl, c02, c2_final, h2_final, Ahi, Alo);

    // decoder (BM=128 x BN=256, scatter epilogue)
    gemm_wide<1><<<dim3((Sz * Bz) / 128, Vz / 256), 256, GEMMD_SMEM>>>(
        Ahi, Alo, dwh, dwl, dec_b, out, Vz);
}

// round 17
// speedup vs baseline: 1.2365x; 1.0137x over previous
#include <cuda_runtime.h>
#include <cuda_bf16.h>
#include <math.h>
#include <stdint.h>

#define Bz 20
#define Sz 256
#define Vz 32000
#define Hz 1024
#define G4H 4096

// ---------------- scratch (static device globals — allocation-free) ----------------
__device__ float g_xproj[Sz * Bz * G4H];                 // [S][B][4H]
__device__ __nv_bfloat16 g_A_hi[Sz * Bz * Hz];           // GEMM A operand (hi)
__device__ __nv_bfloat16 g_A_lo[Sz * Bz * Hz];           // GEMM A operand (lo)
__device__ __nv_bfloat16 g_hAh[2][32 * Hz];              // h state hi (ping-pong)
__device__ __nv_bfloat16 g_hAl[2][32 * Hz];              // h state lo
__device__ __nv_bfloat16 g_w1_hi[G4H * Hz];              // x2h splits
__device__ __nv_bfloat16 g_w1_lo[G4H * Hz];
__device__ __nv_bfloat16 g_w2_hi[G4H * Hz];
__device__ __nv_bfloat16 g_w2_lo[G4H * Hz];
__device__ __nv_bfloat16 g_dw_hi[Vz * Hz];
__device__ __nv_bfloat16 g_dw_lo[Vz * Hz];
__device__ __nv_bfloat16 g_wr1_hi[G4H * Hz];             // h2h permuted splits: row n=d*4+g
__device__ __nv_bfloat16 g_wr1_lo[G4H * Hz];
__device__ __nv_bfloat16 g_wr2_hi[G4H * Hz];
__device__ __nv_bfloat16 g_wr2_lo[G4H * Hz];
__device__ unsigned g_bar;                               // grid barrier counter

// ---------------- PTX helpers (portable) ----------------
__device__ __forceinline__ uint32_t smem_u32(const void* p) {
    uint32_t a;
    asm("{ .reg .u64 t; cvta.to.shared.u64 t, %1; cvt.u32.u64 %0, t; }" : "=r"(a) : "l"(p));
    return a;
}
#define CPASYNC16(dst, src) \
    asm volatile("cp.async.cg.shared.global [%0], [%1], 16;" :: "r"(dst), "l"(src))
#define CPCOMMIT() asm volatile("cp.async.commit_group;" ::: "memory")
#define CPWAIT(n)  asm volatile("cp.async.wait_group %0;" :: "n"(n) : "memory")
#define LDSM4(R, addr)                                                                  \
    asm volatile("ldmatrix.sync.aligned.m8n8.x4.shared.b16 {%0,%1,%2,%3}, [%4];"        \
        : "=r"((R)[0]), "=r"((R)[1]), "=r"((R)[2]), "=r"((R)[3]) : "r"(addr))
#define MMA16816(D, A, B0, B1)                                                          \
    asm volatile("mma.sync.aligned.m16n8k16.row.col.f32.bf16.bf16.f32 "                 \
        "{%0,%1,%2,%3}, {%4,%5,%6,%7}, {%8,%9}, {%0,%1,%2,%3};"                         \
        : "+f"((D)[0]), "+f"((D)[1]), "+f"((D)[2]), "+f"((D)[3])                        \
        : "r"((A)[0]), "r"((A)[1]), "r"((A)[2]), "r"((A)[3]), "r"(B0), "r"(B1))

// ---------------- fp32 -> bf16 hi/lo split helpers ----------------
__device__ __forceinline__ void split4(float4 v, uint2& hi, uint2& lo) {
    float f[4] = {v.x, v.y, v.z, v.w};
    uint32_t h[4], l[4];
#pragma unroll
    for (int i = 0; i < 4; i++) {
        __nv_bfloat16 bh = __float2bfloat16(f[i]);
        __nv_bfloat16 bl = __float2bfloat16(f[i] - __bfloat162float(bh));
        h[i] = __bfloat16_as_ushort(bh);
        l[i] = __bfloat16_as_ushort(bl);
    }
    hi.x = h[0] | (h[1] << 16); hi.y = h[2] | (h[3] << 16);
    lo.x = l[0] | (l[1] << 16); lo.y = l[2] | (l[3] << 16);
}

__global__ void split_w(const float* __restrict__ w, __nv_bfloat16* __restrict__ hi,
                        __nv_bfloat16* __restrict__ lo, int n4) {
    int i = blockIdx.x * 256 + threadIdx.x;
    if (i >= n4) return;
    uint2 h, l;
    split4(reinterpret_cast<const float4*>(w)[i], h, l);
    reinterpret_cast<uint2*>(hi)[i] = h;
    reinterpret_cast<uint2*>(lo)[i] = l;
}

// permuted h2h split: out row n = d*4+g  <-  in row g*1024+d
__global__ void perm_split_w(const float* __restrict__ w, __nv_bfloat16* __restrict__ hi,
                             __nv_bfloat16* __restrict__ lo) {
    int idx = blockIdx.x * 256 + threadIdx.x;
    int n  = idx >> 8;
    int k4 = idx & 255;
    int d = n >> 2, g = n & 3;
    uint2 h, l;
    split4(reinterpret_cast<const float4*>(w)[(g * Hz + d) * 256 + k4], h, l);
    reinterpret_cast<uint2*>(hi)[n * 256 + k4] = h;
    reinterpret_cast<uint2*>(lo)[n * 256 + k4] = l;
}

// split h0 fp32 [20][1024] into hA buffer rows 0..19; also clears the grid barrier
__global__ void split_h0(const float* __restrict__ h0, __nv_bfloat16* __restrict__ hi,
                         __nv_bfloat16* __restrict__ lo) {
    if (blockIdx.x == 0 && threadIdx.x == 0) g_bar = 0u;
    int i = blockIdx.x * 256 + threadIdx.x;
    uint2 h, l;
    split4(reinterpret_cast<const float4*>(h0)[i], h, l);
    reinterpret_cast<uint2*>(hi)[i] = h;
    reinterpret_cast<uint2*>(lo)[i] = l;
}

// ---------------- embedding gather -> A hi/lo directly ----------------
__global__ void embed_split(const int* __restrict__ ids, const float* __restrict__ emb,
                            __nv_bfloat16* __restrict__ Ahi, __nv_bfloat16* __restrict__ Alo) {
    int gid = blockIdx.x * 256 + threadIdx.x;
    int c4  = gid & 255;
    int sb  = gid >> 8;
    int b   = sb % Bz;
    int s   = sb / Bz;
    int tok = ids[b * Sz + s];
    float4 v = reinterpret_cast<const float4*>(emb)[(size_t)tok * 256 + c4];
    uint2 h, l;
    split4(v, h, l);
    reinterpret_cast<uint2*>(Ahi)[gid] = h;
    reinterpret_cast<uint2*>(Alo)[gid] = l;
}

// ---------------- HMMA bf16-split GEMM: BM=128, BN=256, 512 threads ----------------
// 16 warps (4m x 4n), warp tile 32x64; per-thread acc 64 regs -> no spills,
// 4 warps/SMSP -> ldmatrix latency hidden. Same validated fragment math.
// MODE 0: C row-major [M][N].  MODE 1: decoder scatter m=s*B+b -> C[(b*S+s)*N + n].
#define BK 32
#define SROW 80
#define DTA 10240                         // A tile bytes (128 rows * SROW)
#define DTB 20480                         // W tile bytes (256 rows * SROW)
#define DSTAGE (2 * DTA + 2 * DTB)        // 61440 per stage
#define GEMMD_SMEM (2 * DSTAGE)           // 122880

template <int MODE>
__global__ __launch_bounds__(512, 1) void gemm_wide(
    const __nv_bfloat16* __restrict__ Ahi, const __nv_bfloat16* __restrict__ Alo,
    const __nv_bfloat16* __restrict__ Whi, const __nv_bfloat16* __restrict__ Wlo,
    const float* __restrict__ bias, float* __restrict__ C, int N) {
    extern __shared__ char smdyn[];
    const uint32_t sb = smem_u32(smdyn);
    const int tid  = threadIdx.x;
    const int wid  = tid >> 5;              // 0..15
    const int lane = tid & 31;
    const int bm   = blockIdx.x * 128;
    const int bn   = blockIdx.y * 256;
    const int wm   = (wid & 3) * 32;        // 4 warps along M
    const int wn   = (wid >> 2) * 64;       // 4 warps along N

    float acc[2][8][4];
#pragma unroll
    for (int mf = 0; mf < 2; mf++)
#pragma unroll
        for (int nf = 0; nf < 8; nf++)
#pragma unroll
            for (int r = 0; r < 4; r++) acc[mf][nf][r] = 0.0f;

    const uint32_t a_off = (uint32_t)((wm + (lane & 15)) * SROW + (lane >> 4) * 16);
    const uint32_t b_off = (uint32_t)((wn + (lane & 7) + ((lane >> 4) << 3)) * SROW +
                                      ((lane >> 3) & 1) * 16);

    auto prefetch = [&](int ch, int buf) {
        const int kt = ch * BK;
        const uint32_t base = sb + buf * DSTAGE;
#pragma unroll
        for (int i = 0; i < 6; i++) {
            int id = tid + i * 512;               // 0..3071
            int r4 = id >> 2;                     // row 0..767
            int c4 = id & 3;
            const __nv_bfloat16* src;
            uint32_t dst;
            if (r4 < 256) {                       // A hi(0..127) / lo(128..255)
                int sel = r4 >> 7;
                int r   = r4 & 127;
                src = (sel ? Alo : Ahi) + (size_t)(bm + r) * Hz + kt + c4 * 8;
                dst = base + (uint32_t)(sel * DTA) + (uint32_t)(r * SROW + c4 * 16);
            } else {                              // W hi(256..511) / lo(512..767)
                int sel = (r4 - 256) >> 8;
                int r   = (r4 - 256) & 255;
                src = (sel ? Wlo : Whi) + (size_t)(bn + r) * Hz + kt + c4 * 8;
                dst = base + 2u * DTA + (uint32_t)(sel * DTB) +
                      (uint32_t)(r * SROW + c4 * 16);
            }
            CPASYNC16(dst, src);
        }
    };

    prefetch(0, 0);
    CPCOMMIT();

    const int NCH = Hz / BK;                      // 32
    for (int ch = 0; ch < NCH; ch++) {
        const int buf = ch & 1;
        if (ch + 1 < NCH) {
            prefetch(ch + 1, buf ^ 1);
            CPCOMMIT();
            CPWAIT(1);
        } else {
            CPWAIT(0);
        }
        __syncthreads();

        const uint32_t ah_b = sb + buf * DSTAGE;
        const uint32_t al_b = ah_b + DTA;
        const uint32_t wh_b = ah_b + 2 * DTA;
        const uint32_t wl_b = wh_b + DTB;

#pragma unroll
        for (int k16 = 0; k16 < 2; k16++) {
            const uint32_t ko = k16 * 32;
            uint32_t ah[2][4], al[2][4];
#pragma unroll
            for (int mf = 0; mf < 2; mf++) {
                LDSM4(ah[mf], ah_b + a_off + mf * 16 * SROW + ko);
                LDSM4(al[mf], al_b + a_off + mf * 16 * SROW + ko);
            }
#pragma unroll
            for (int g2 = 0; g2 < 2; g2++) {      // two nf2-pairs of the 64-wide tile
                uint32_t bh[2][4], bl[2][4];
#pragma unroll
                for (int j = 0; j < 2; j++) {
                    int nf2 = g2 * 2 + j;
                    LDSM4(bh[j], wh_b + b_off + nf2 * 16 * SROW + ko);
                    LDSM4(bl[j], wl_b + b_off + nf2 * 16 * SROW + ko);
                }
#pragma unroll
                for (int mf = 0; mf < 2; mf++)
#pragma unroll
                    for (int q = 0; q < 4; q++) {
                        int nf = g2 * 4 + q;
                        int j  = q >> 1;
                        uint32_t b0h = bh[j][(q & 1) * 2 + 0];
                        uint32_t b1h = bh[j][(q & 1) * 2 + 1];
                        uint32_t b0l = bl[j][(q & 1) * 2 + 0];
                        uint32_t b1l = bl[j][(q & 1) * 2 + 1];
                        MMA16816(acc[mf][nf], ah[mf], b0h, b1h);
                        MMA16816(acc[mf][nf], ah[mf], b0l, b1l);
                        MMA16816(acc[mf][nf], al[mf], b0h, b1h);
                    }
            }
        }
        __syncthreads();
    }

    const int g  = lane >> 2;
    const int tg = lane & 3;
#pragma unroll
    for (int mf = 0; mf < 2; mf++) {
        int m0 = bm + wm + mf * 16 + g;
        int m1 = m0 + 8;
        size_t rb0, rb1;
        if (MODE == 0) {
            rb0 = (size_t)m0 * N;
            rb1 = (size_t)m1 * N;
        } else {
            rb0 = (size_t)((m0 % Bz) * Sz + m0 / Bz) * N;
            rb1 = (size_t)((m1 % Bz) * Sz + m1 / Bz) * N;
        }
#pragma unroll
        for (int nf = 0; nf < 8; nf++) {
            int col = bn + wn + nf * 8 + tg * 2;
            float2 bv = *reinterpret_cast<const float2*>(&bias[col]);
            float* a = acc[mf][nf];
            *reinterpret_cast<float2*>(&C[rb0 + col]) = make_float2(a[0] + bv.x, a[1] + bv.y);
            *reinterpret_cast<float2*>(&C[rb1 + col]) = make_float2(a[2] + bv.x, a[3] + bv.y);
        }
    }
}

// ---------------- persistent LSTM layer kernel (R13: atomic barrier + xp prefetch) --
#define PROWB 2064
#define WH_OFF 0
#define WL_OFF 66048
#define HB_OFF 132096
#define HL_OFF 173376
#define ZR_OFF 214656
#define RD_OFF 216720
#define XP_OFF 224912                    // two 2560B xp buffers
#define BH_OFF 230032
#define CS_OFF 230160
#define PERS_SMEM 230800

__global__ __launch_bounds__(256, 1) void lstm_layer_persistent(
    const __nv_bfloat16* __restrict__ Wph, const __nv_bfloat16* __restrict__ Wpl,
    const float* __restrict__ bh, const float* __restrict__ xp_base,
    __nv_bfloat16* __restrict__ hAh, __nv_bfloat16* __restrict__ hAl,   // [2][32*Hz]
    const float* __restrict__ c_in,
    float* __restrict__ c_final, float* __restrict__ h_final,
    __nv_bfloat16* __restrict__ seq_hi, __nv_bfloat16* __restrict__ seq_lo) {
    extern __shared__ char smdyn[];
    const uint32_t sb = smem_u32(smdyn);
    const int tid  = threadIdx.x;
    const int wid  = tid >> 5;
    const int lane = tid & 31;
    const int blk  = blockIdx.x;
    const int k4   = wid >> 1;
    const int n2   = wid & 1;

    // --- one-time setup: W resident + xp(0) stage, zero row, bias, c state ---
#pragma unroll
    for (int i = 0; i < 32; i++) {
        int c   = tid + i * 256;
        int sel = c >> 12;
        int u   = c & 4095;
        int r   = u >> 7;
        int col = u & 127;
        const __nv_bfloat16* src = (sel ? Wpl : Wph) + (size_t)(blk * 32 + r) * Hz + col * 8;
        CPASYNC16(sb + (sel ? WL_OFF : WH_OFF) + r * PROWB + col * 16, src);
    }
    if (tid < 160) {                      // xp(0) -> buffer 0
        int run = tid >> 1, half = tid & 1;
        const char* src = (const char*)(xp_base + (size_t)(run >> 2) * G4H +
                                        (run & 3) * Hz + blk * 8) + half * 16;
        CPASYNC16(sb + XP_OFF + tid * 16, src);
    }
    CPCOMMIT();
    if (tid < 129)
        *reinterpret_cast<float4*>(smdyn + ZR_OFF + tid * 16) = make_float4(0.f, 0.f, 0.f, 0.f);
    if (tid < 32)
        reinterpret_cast<float*>(smdyn + BH_OFF)[tid] = bh[(tid >> 3) * Hz + blk * 8 + (tid & 7)];
    if (tid < 8 * Bz)
        reinterpret_cast<float*>(smdyn + CS_OFF)[tid] =
            c_in[(tid >> 3) * Hz + blk * 8 + (tid & 7)];
    CPWAIT(0);
    __syncthreads();

    // per-lane invariant ldmatrix offsets
    uint32_t a_row_hi[2], a_row_lo[2];
#pragma unroll
    for (int mf = 0; mf < 2; mf++) {
        int r = mf * 16 + (lane & 15);
        a_row_hi[mf] = (r < Bz) ? (sb + HB_OFF + r * PROWB) : (sb + ZR_OFF);
        a_row_lo[mf] = (r < Bz) ? (sb + HL_OFF + r * PROWB) : (sb + ZR_OFF);
    }
    const uint32_t a_koff0 = (uint32_t)((lane >> 4) * 16);
    const uint32_t b_row = sb + (uint32_t)((n2 * 16 + (lane & 7) + ((lane >> 4) << 3)) * PROWB) +
                           (uint32_t)(((lane >> 3) & 1) * 16);
    float* red = reinterpret_cast<float*>(smdyn + RD_OFF);
    float* bhs = reinterpret_cast<float*>(smdyn + BH_OFF);
    float* cs  = reinterpret_cast<float*>(smdyn + CS_OFF);

    for (int s = 0; s < Sz; s++) {
        const __nv_bfloat16* hih = hAh + (size_t)(s & 1) * 32 * Hz;
        const __nv_bfloat16* hil = hAl + (size_t)(s & 1) * 32 * Hz;
        __nv_bfloat16* hoh = hAh + (size_t)((s + 1) & 1) * 32 * Hz;
        __nv_bfloat16* hol = hAl + (size_t)((s + 1) & 1) * 32 * Hz;

        // issue h loads: 4 k-chunk groups; kc3 also prefetches xp(s+1)
#pragma unroll
        for (int kc = 0; kc < 4; kc++) {
#pragma unroll
            for (int i = 0; i < 5; i++) {
                int c   = tid + i * 256;
                int sel = c >= 640;
                int u   = c - sel * 640;
                int r   = u >> 5;
                int col = u & 31;
                const char* src = (const char*)(sel ? hil : hih) + r * 2048 + kc * 512 + col * 16;
                CPASYNC16(sb + (sel ? HL_OFF : HB_OFF) + r * PROWB + kc * 512 + col * 16, src);
            }
            if (kc == 3 && s + 1 < Sz && tid < 160) {
                const float* xpn = xp_base + (size_t)(s + 1) * Bz * G4H;
                int run = tid >> 1, half = tid & 1;
                const char* src = (const char*)(xpn + (size_t)(run >> 2) * G4H +
                                                (run & 3) * Hz + blk * 8) + half * 16;
                CPASYNC16(sb + XP_OFF + ((s + 1) & 1) * 2560 + tid * 16, src);
            }
            CPCOMMIT();
        }

        float acc[2][2][4];
#pragma unroll
        for (int mf = 0; mf < 2; mf++)
#pragma unroll
            for (int nf = 0; nf < 2; nf++)
#pragma unroll
                for (int r = 0; r < 4; r++) acc[mf][nf][r] = 0.0f;

#pragma unroll
        for (int kc = 0; kc < 4; kc++) {
            if (kc == 0)      CPWAIT(3);
            else if (kc == 1) CPWAIT(2);
            else if (kc == 2) CPWAIT(1);
            else              CPWAIT(0);
            __syncthreads();
#pragma unroll
            for (int ks = 0; ks < 4; ks++) {
                const uint32_t kb = (uint32_t)(kc * 512 + k4 * 128 + ks * 32);
                uint32_t ah[2][4], al[2][4], bhv[4], blv[4];
#pragma unroll
                for (int mf = 0; mf < 2; mf++) {
                    LDSM4(ah[mf], a_row_hi[mf] + a_koff0 + kb);
                    LDSM4(al[mf], a_row_lo[mf] + a_koff0 + kb);
                }
                LDSM4(bhv, b_row + WH_OFF + kb);
                LDSM4(blv, b_row + WL_OFF + kb);
#pragma unroll
                for (int mf = 0; mf < 2; mf++)
#pragma unroll
                    for (int nf = 0; nf < 2; nf++) {
                        uint32_t b0h = bhv[nf * 2], b1h = bhv[nf * 2 + 1];
                        uint32_t b0l = blv[nf * 2], b1l = blv[nf * 2 + 1];
                        MMA16816(acc[mf][nf], ah[mf], b0h, b1h);
                        MMA16816(acc[mf][nf], ah[mf], b0l, b1l);
                        MMA16816(acc[mf][nf], al[mf], b0h, b1h);
                    }
            }
        }

        // two-round k-split reduction into red[2][32][32]
        const int g  = lane >> 2;
        const int tg = lane & 3;
        if (k4 >= 2) {
#pragma unroll
            for (int mf = 0; mf < 2; mf++)
#pragma unroll
                for (int nf = 0; nf < 2; nf++)
#pragma unroll
                    for (int r = 0; r < 4; r++) {
                        int m = g + ((r >> 1) & 1) * 8 + mf * 16;
                        int n = n2 * 16 + nf * 8 + tg * 2 + (r & 1);
                        red[((k4 - 2) * 32 + m) * 32 + n] = acc[mf][nf][r];
                    }
        }
        __syncthreads();
        if (k4 < 2) {
#pragma unroll
            for (int mf = 0; mf < 2; mf++)
#pragma unroll
                for (int nf = 0; nf < 2; nf++)
#pragma unroll
                    for (int r = 0; r < 4; r++) {
                        int m = g + ((r >> 1) & 1) * 8 + mf * 16;
                        int n = n2 * 16 + nf * 8 + tg * 2 + (r & 1);
                        int idx = (k4 * 32 + m) * 32 + n;
                        red[idx] += acc[mf][nf][r];
                    }
        }
        __syncthreads();

        // fused cell update: 8 dims x 20 batches (xp staged LAST step -> buf s&1)
        if (tid < 8 * Bz) {
            float* xps = reinterpret_cast<float*>(smdyn + XP_OFF + (s & 1) * 2560);
            int dl = tid & 7;
            int b  = tid >> 3;
            int d  = blk * 8 + dl;
            float gate[4];
#pragma unroll
            for (int gg = 0; gg < 4; gg++) {
                int n = dl * 4 + gg;
                gate[gg] = red[(0 * 32 + b) * 32 + n] + red[(1 * 32 + b) * 32 + n] +
                           xps[(b * 4 + gg) * 8 + dl] + bhs[gg * 8 + dl];
            }
            float ii = 1.0f / (1.0f + expf(-gate[0]));
            float ff = 1.0f / (1.0f + expf(-gate[1]));
            float gv = tanhf(gate[2]);
            float oo = 1.0f / (1.0f + expf(-gate[3]));
            float cc = cs[tid] * ff + ii * gv;
            float hh = oo * tanhf(cc);
            cs[tid] = cc;
            __nv_bfloat16 bhh = __float2bfloat16(hh);
            __nv_bfloat16 blo = __float2bfloat16(hh - __bfloat162float(bhh));
            hoh[b * Hz + d] = bhh;
            hol[b * Hz + d] = blo;
            seq_hi[(size_t)s * Bz * Hz + b * Hz + d] = bhh;
            seq_lo[(size_t)s * Bz * Hz + b * Hz + d] = blo;
            if (s == Sz - 1) {
                c_final[b * Hz + d] = cc;
                h_final[b * Hz + d] = hh;
            }
        }

        // single grid barrier per step (skip after last) — R13-proven form
        if (s < Sz - 1) {
            __syncthreads();
            if (tid == 0) {
                __threadfence();
                atomicAdd(&g_bar, 1u);
                unsigned target = (unsigned)(s + 1) * (unsigned)gridDim.x;
                volatile unsigned* vb = &g_bar;
                while (*vb < target) {}
            }
            __syncthreads();
        }
    }
}

// ---------------- launch (lstm L1 kept as launch #5 for ncu capture) ----------------
extern "C" void kernel_launch(void* const* d_in, const int* in_sizes, int n_in,
                              void* d_out, int out_size) {
    const int*   ids    = (const int*)d_in[0];
    const float* emb    = (const float*)d_in[1];
    const float* x2h_w1 = (const float*)d_in[2];
    const float* x2h_b1 = (const float*)d_in[3];
    const float* h2h_w1 = (const float*)d_in[4];
    const float* h2h_b1 = (const float*)d_in[5];
    const float* x2h_w2 = (const float*)d_in[6];
    const float* x2h_b2 = (const float*)d_in[7];
    const float* h2h_w2 = (const float*)d_in[8];
    const float* h2h_b2 = (const float*)d_in[9];
    const float* dec_w  = (const float*)d_in[10];
    const float* dec_b  = (const float*)d_in[11];
    const float* h01    = (const float*)d_in[12];
    const float* c01    = (const float*)d_in[13];
    const float* h02    = (const float*)d_in[14];
    const float* c02    = (const float*)d_in[15];
    float* out = (float*)d_out;

    float* xproj;
    __nv_bfloat16 *Ahi, *Alo, *w1h, *w1l, *w2h, *w2l, *dwh, *dwl;
    __nv_bfloat16 *hAh, *hAl, *wr1h, *wr1l, *wr2h, *wr2l;
    cudaGetSymbolAddress((void**)&xproj, g_xproj);
    cudaGetSymbolAddress((void**)&Ahi, g_A_hi);
    cudaGetSymbolAddress((void**)&Alo, g_A_lo);
    cudaGetSymbolAddress((void**)&w1h, g_w1_hi);
    cudaGetSymbolAddress((void**)&w1l, g_w1_lo);
    cudaGetSymbolAddress((void**)&w2h, g_w2_hi);
    cudaGetSymbolAddress((void**)&w2l, g_w2_lo);
    cudaGetSymbolAddress((void**)&dwh, g_dw_hi);
    cudaGetSymbolAddress((void**)&dwl, g_dw_lo);
    cudaGetSymbolAddress((void**)&hAh, g_hAh);
    cudaGetSymbolAddress((void**)&hAl, g_hAl);
    cudaGetSymbolAddress((void**)&wr1h, g_wr1_hi);
    cudaGetSymbolAddress((void**)&wr1l, g_wr1_lo);
    cudaGetSymbolAddress((void**)&wr2h, g_wr2_hi);
    cudaGetSymbolAddress((void**)&wr2l, g_wr2_lo);

    cudaFuncSetAttribute(lstm_layer_persistent,
                         cudaFuncAttributeMaxDynamicSharedMemorySize, PERS_SMEM);
    cudaFuncSetAttribute(gemm_wide<0>, cudaFuncAttributeMaxDynamicSharedMemorySize, GEMMD_SMEM);
    cudaFuncSetAttribute(gemm_wide<1>, cudaFuncAttributeMaxDynamicSharedMemorySize, GEMMD_SMEM);

    float* h1_final = out + (size_t)Bz * Sz * Vz;
    float* c1_final = h1_final + Bz * Hz;
    float* h2_final = c1_final + Bz * Hz;
    float* c2_final = h2_final + Bz * Hz;

    // #0 layer-1 x2h split
    split_w<<<(G4H * Hz / 4 + 255) / 256, 256>>>(x2h_w1, w1h, w1l, G4H * Hz / 4);
    // #1 layer-1 h2h permuted split
    perm_split_w<<<G4H, 256>>>(h2h_w1, wr1h, wr1l);
    // #2 embedding -> A hi/lo
    embed_split<<<Sz * Bz, 256>>>(ids, emb, Ahi, Alo);
    // #3 x-projection layer 1 (512 threads)
    gemm_wide<0><<<dim3((Sz * Bz) / 128, G4H / 256), 512, GEMMD_SMEM>>>(
        Ahi, Alo, w1h, w1l, x2h_b1, xproj, G4H);
    // #4 h0 split (also clears g_bar)
    split_h0<<<20, 256>>>(h01, hAh, hAl);
    // #5 layer-1 recurrence
    lstm_layer_persistent<<<128, 256, PERS_SMEM>>>(
        wr1h, wr1l, h2h_b1, xproj, hAh, hAl, c01, c1_final, h1_final, Ahi, Alo);

    // deferred prep for layer 2 / decoder
    split_w<<<(G4H * Hz / 4 + 255) / 256, 256>>>(x2h_w2, w2h, w2l, G4H * Hz / 4);
    perm_split_w<<<G4H, 256>>>(h2h_w2, wr2h, wr2l);
    split_w<<<(Vz * Hz / 4 + 255) / 256, 256>>>(dec_w, dwh, dwl, Vz * Hz / 4);

    // x-projection layer 2
    gemm_wide<0><<<dim3((Sz * Bz) / 128, G4H / 256), 512, GEMMD_SMEM>>>(
        Ahi, Alo, w2h, w2l, x2h_b2, xproj, G4H);

    // layer-2 recurrence
    split_h0<<<20, 256>>>(h02, hAh, hAl);
    lstm_layer_persistent<<<128, 256, PERS_SMEM>>>(
        wr2h, wr2l, h2h_b2, xproj, hAh, hAl, c02, c2_final, h2_final, Ahi, Alo);

    // decoder (BM=128 x BN=256, scatter epilogue, 512 threads)
    gemm_wide<1><<<dim3((Sz * Bz) / 128, Vz / 256), 512, GEMMD_SMEM>>>(
        Ahi, Alo, dwh, dwl, dec_b, out, Vz);
}